// round 4
// baseline (speedup 1.0000x reference)
#include <cuda_runtime.h>
#include <cstddef>

#define N_NODES 50000
#define N_EDGES 800000
#define N_GRAPHS 50
#define NODES_PER_GRAPH 1000

// Scratch (device globals; allocation rules forbid cudaMalloc)
__device__ float g_e[(size_t)N_EDGES * 64];     // 204.8 MB: e0 -> e1 -> e2 in place
__device__ float g_x1[(size_t)N_NODES * 128];   // 25.6 MB
__device__ float g_x2[(size_t)N_NODES * 128];   // 25.6 MB

struct Seg {
    const float* base;    // row-major [*, K]
    const int*   gather;  // nullptr = identity row index
    const float* W;       // [K, BN] row-major
    int K;
};

__device__ __forceinline__ unsigned long long pack2(float v) {
    unsigned long long r;
    asm("mov.b64 %0, {%1, %1};" : "=l"(r) : "f"(v));
    return r;
}
__device__ __forceinline__ void ffma2(unsigned long long& d,
                                      unsigned long long a,
                                      unsigned long long b) {
    asm("fma.rn.f32x2 %0, %1, %2, %0;" : "+l"(d) : "l"(a), "l"(b));
}
__device__ __forceinline__ float lo2(unsigned long long v) {
    float2 f = *(float2*)&v; return f.x;
}
__device__ __forceinline__ float hi2(unsigned long long v) {
    float2 f = *(float2*)&v; return f.y;
}

// Pipelined gather-GEMM, packed f32x2 accumulation.
// 512 threads, BM=128 rows/block, BK=16.
// Warp w handles rows w*8..w*8+7 (4 row-pairs); lane handles TN cols.
// 2-stage pipeline: LDG t+2 (regs) / STS t+1 (alt smem buf) / compute t; 1 sync per tile.
template<int BN, int NSEG, bool SCATTER>
__global__ __launch_bounds__(512, 1) void gemm_kernel(
    Seg s0, Seg s1, Seg s2,
    const float* __restrict__ bias, int relu_out,
    float* __restrict__ out, const int* __restrict__ scat_idx, int M)
{
    constexpr int BM = 128, BK = 16;
    constexpr int TN = BN / 32;         // 4 (BN=128) or 2 (BN=64)
    constexpr int PR = 4;               // 4 row-pairs = 8 rows per warp
    constexpr int ASTR = BM + 4;        // 132 floats: row start 528B, 16B aligned

    __shared__ float As[2][BK][ASTR];
    __shared__ float Ws[2][BK * BN];
    __shared__ int   ridx[NSEG][BM];
    __shared__ int   sidx[BM];

    Seg segs[3] = {s0, s1, s2};

    const int tid  = threadIdx.x;
    const int warp = tid >> 5;
    const int lane = tid & 31;
    const int row0 = blockIdx.x * BM;

    if (tid < BM) {
        int r = row0 + tid;
        bool ok = r < M;
        #pragma unroll
        for (int s = 0; s < NSEG; s++) {
            const int* g = segs[s].gather;
            ridx[s][tid] = ok ? (g ? g[r] : r) : 0;
        }
        if (SCATTER) sidx[tid] = ok ? scat_idx[r] : 0;
    }
    __syncthreads();

    // tile map (flattened across segments)
    const int T0 = segs[0].K / BK;
    const int T1 = T0 + ((NSEG > 1) ? segs[1].K / BK : 0);
    const int T  = T1 + ((NSEG > 2) ? segs[2].K / BK : 0);

    const int arow = tid >> 2;          // 0..127
    const int aq   = tid & 3;           // k-quarter (4 floats)

    float4 afrag, wfrag;
    bool   wact = (tid * 4 < BK * BN);

    auto issue = [&](int t) {
        int s, k0;
        if (NSEG > 2 && t >= T1)      { s = 2; k0 = (t - T1) * BK; }
        else if (NSEG > 1 && t >= T0) { s = 1; k0 = (t - T0) * BK; }
        else                          { s = 0; k0 = t * BK; }
        const Seg& sg = segs[s];
        afrag = *(const float4*)(sg.base + (size_t)ridx[s][arow] * sg.K + k0 + aq * 4);
        if (wact)
            wfrag = *(const float4*)(sg.W + (size_t)k0 * BN + tid * 4);
    };
    auto store = [&](int buf) {
        As[buf][aq * 4 + 0][arow] = afrag.x;
        As[buf][aq * 4 + 1][arow] = afrag.y;
        As[buf][aq * 4 + 2][arow] = afrag.z;
        As[buf][aq * 4 + 3][arow] = afrag.w;
        if (wact)
            *(float4*)(&Ws[buf][tid * 4]) = wfrag;
    };

    unsigned long long acc2[PR][TN];
    #pragma unroll
    for (int p = 0; p < PR; p++)
        #pragma unroll
        for (int j = 0; j < TN; j++) acc2[p][j] = 0ull;

    // prologue
    issue(0); store(0);
    if (T > 1) issue(1);
    __syncthreads();

    for (int t = 0; t < T; t++) {
        int buf = t & 1;
        if (t + 1 < T) store(buf ^ 1);
        if (t + 2 < T) issue(t + 2);
        // compute tile t
        #pragma unroll
        for (int k = 0; k < BK; k++) {
            ulonglong2 a01 = *(const ulonglong2*)&As[buf][k][warp * 8];
            ulonglong2 a23 = *(const ulonglong2*)&As[buf][k][warp * 8 + 4];
            unsigned long long ar[PR] = {a01.x, a01.y, a23.x, a23.y};
            unsigned long long bd[TN];
            if (TN == 4) {
                float4 bv = *(const float4*)&Ws[buf][k * BN + lane * 4];
                bd[0] = pack2(bv.x); bd[1] = pack2(bv.y);
                bd[2] = pack2(bv.z); bd[3] = pack2(bv.w);
            } else {
                float2 bv = *(const float2*)&Ws[buf][k * BN + lane * 2];
                bd[0] = pack2(bv.x); bd[1] = pack2(bv.y);
            }
            #pragma unroll
            for (int p = 0; p < PR; p++)
                #pragma unroll
                for (int j = 0; j < TN; j++)
                    ffma2(acc2[p][j], ar[p], bd[j]);
        }
        __syncthreads();
    }

    // ---- epilogue (8 rows per warp) ----
    if (SCATTER) {
        #pragma unroll
        for (int h = 0; h < 8; h++) {
            int rl_ = warp * 8 + h;
            if (row0 + rl_ < M) {
                float* op = out + (size_t)sidx[rl_] * BN + lane * TN;
                int p = h >> 1, c = h & 1;
                if (TN == 4) {
                    float v0 = c ? hi2(acc2[p][0]) : lo2(acc2[p][0]);
                    float v1 = c ? hi2(acc2[p][1]) : lo2(acc2[p][1]);
                    float v2 = c ? hi2(acc2[p][2]) : lo2(acc2[p][2]);
                    float v3 = c ? hi2(acc2[p][3]) : lo2(acc2[p][3]);
                    asm volatile("red.global.add.v4.f32 [%0], {%1,%2,%3,%4};"
                                 :: "l"(op), "f"(v0), "f"(v1), "f"(v2), "f"(v3)
                                 : "memory");
                } else {
                    float v0 = c ? hi2(acc2[p][0]) : lo2(acc2[p][0]);
                    float v1 = c ? hi2(acc2[p][1]) : lo2(acc2[p][1]);
                    asm volatile("red.global.add.v2.f32 [%0], {%1,%2};"
                                 :: "l"(op), "f"(v0), "f"(v1)
                                 : "memory");
                }
            }
        }
    } else {
        float bv[TN];
        #pragma unroll
        for (int j = 0; j < TN; j++) bv[j] = bias ? bias[lane * TN + j] : 0.f;
        #pragma unroll
        for (int h = 0; h < 8; h++) {
            int r = row0 + warp * 8 + h;
            if (r < M) {
                int p = h >> 1, c = h & 1;
                if (TN == 4) {
                    float4 o;
                    o.x = (c ? hi2(acc2[p][0]) : lo2(acc2[p][0])) + bv[0];
                    o.y = (c ? hi2(acc2[p][1]) : lo2(acc2[p][1])) + bv[1];
                    o.z = (c ? hi2(acc2[p][2]) : lo2(acc2[p][2])) + bv[2];
                    o.w = (c ? hi2(acc2[p][3]) : lo2(acc2[p][3])) + bv[3];
                    if (relu_out) {
                        o.x = fmaxf(o.x, 0.f); o.y = fmaxf(o.y, 0.f);
                        o.z = fmaxf(o.z, 0.f); o.w = fmaxf(o.w, 0.f);
                    }
                    *(float4*)(out + (size_t)r * BN + lane * 4) = o;
                } else {
                    float2 o;
                    o.x = (c ? hi2(acc2[p][0]) : lo2(acc2[p][0])) + bv[0];
                    o.y = (c ? hi2(acc2[p][1]) : lo2(acc2[p][1])) + bv[1];
                    if (relu_out) { o.x = fmaxf(o.x, 0.f); o.y = fmaxf(o.y, 0.f); }
                    *(float2*)(out + (size_t)r * BN + lane * 2) = o;
                }
            }
        }
    }
}

// in-place relu over n floats (n % 4 == 0)
__global__ __launch_bounds__(256) void relu_kernel(float* __restrict__ p, int n)
{
    int i = (blockIdx.x * 256 + threadIdx.x) * 4;
    if (i < n) {
        float4 v = *(float4*)(p + i);
        v.x = fmaxf(v.x, 0.f); v.y = fmaxf(v.y, 0.f);
        v.z = fmaxf(v.z, 0.f); v.w = fmaxf(v.w, 0.f);
        *(float4*)(p + i) = v;
    }
}

// out[g] = relu(x2[g*1000]) @ ws3 + bs3   (50 x 256, K=128)
__global__ __launch_bounds__(256) void master_node_kernel(
    const float* __restrict__ x2, const float* __restrict__ ws3,
    const float* __restrict__ bs3, float* __restrict__ out)
{
    int g = blockIdx.x;
    int c = threadIdx.x;
    const float* xr = x2 + (size_t)g * NODES_PER_GRAPH * 128;
    float acc = bs3[c];
    #pragma unroll 8
    for (int k = 0; k < 128; k++)
        acc += fmaxf(xr[k], 0.f) * ws3[(size_t)k * 256 + c];
    out[(size_t)g * 256 + c] = acc;
}

// For edges with dst % 1000 == 0 (~800 of 800K):
// out[dst/1000] += relu(x2[src]) @ wmx3 + e2 @ wme3
__global__ __launch_bounds__(256) void master_edge_kernel(
    const float* __restrict__ x2, const float* __restrict__ e2,
    const int* __restrict__ src, const int* __restrict__ dst,
    const float* __restrict__ wmx3, const float* __restrict__ wme3,
    float* __restrict__ out)
{
    __shared__ float buf[8][192];
    int warp = threadIdx.x >> 5, lane = threadIdx.x & 31;
    int e0 = (blockIdx.x * 8 + warp) * 32;
    if (e0 >= N_EDGES) return;
    int e = e0 + lane;
    int d = dst[e];
    bool hit = (d % NODES_PER_GRAPH == 0);
    unsigned mask = __ballot_sync(0xffffffffu, hit);
    while (mask) {
        int b = __ffs(mask) - 1;
        mask &= mask - 1;
        int eh = e0 + b;
        int sh = src[eh];
        int dh = __shfl_sync(0xffffffffu, d, b);
        for (int k = lane; k < 128; k += 32)
            buf[warp][k] = fmaxf(x2[(size_t)sh * 128 + k], 0.f);
        for (int k = lane; k < 64; k += 32)
            buf[warp][128 + k] = e2[(size_t)eh * 64 + k];
        __syncwarp();
        float acc[8];
        #pragma unroll
        for (int i = 0; i < 8; i++) acc[i] = 0.f;
        for (int k = 0; k < 128; k++) {
            float a = buf[warp][k];
            const float* wr = wmx3 + (size_t)k * 256;
            #pragma unroll
            for (int i = 0; i < 8; i++) acc[i] += a * wr[lane + i * 32];
        }
        for (int k = 0; k < 64; k++) {
            float a = buf[warp][128 + k];
            const float* wr = wme3 + (size_t)k * 256;
            #pragma unroll
            for (int i = 0; i < 8; i++) acc[i] += a * wr[lane + i * 32];
        }
        float* op = out + (size_t)(dh / NODES_PER_GRAPH) * 256;
        #pragma unroll
        for (int i = 0; i < 8; i++) atomicAdd(op + lane + i * 32, acc[i]);
        __syncwarp();
    }
}

extern "C" void kernel_launch(void* const* d_in, const int* in_sizes, int n_in,
                              void* d_out, int out_size)
{
    const float* x         = (const float*)d_in[0];
    const int*   edge_idx  = (const int*)d_in[1];
    const float* edge_attr = (const float*)d_in[2];
    const float* w_proj    = (const float*)d_in[4];
    const float* b_proj    = (const float*)d_in[5];
    const float* P[30];
    for (int i = 0; i < 30 && i < n_in; i++) P[i] = (const float*)d_in[i];

    const int* src = edge_idx;
    const int* dst = edge_idx + N_EDGES;
    float* out = (float*)d_out;

    void* p;
    cudaGetSymbolAddress(&p, g_e);  float* e_p  = (float*)p;
    cudaGetSymbolAddress(&p, g_x1); float* x1_p = (float*)p;
    cudaGetSymbolAddress(&p, g_x2); float* x2_p = (float*)p;

    Seg z = {nullptr, nullptr, nullptr, 0};
    const int EG = N_EDGES / 128;                 // 6250 blocks
    const int NG = (N_NODES + 127) / 128;         // 391 blocks

    // 1) e0 = edge_attr @ w_proj + b_proj
    {
        Seg a = {edge_attr, nullptr, w_proj, 128};
        gemm_kernel<64, 1, false><<<EG, 512>>>(a, z, z, b_proj, 0, e_p, nullptr, N_EDGES);
    }
    // 2) x1 = x @ ws1 + bs1
    {
        Seg a = {x, nullptr, P[6], 256};
        gemm_kernel<128, 1, false><<<NG, 512>>>(a, z, z, P[7], 0, x1_p, nullptr, N_NODES);
    }
    // 3) x1[dst] += x[src] @ wmx1 + e0 @ wme1
    {
        Seg a = {x, src, P[8], 256};
        Seg b = {e_p, nullptr, P[9], 64};
        gemm_kernel<128, 2, true><<<EG, 512>>>(a, b, z, nullptr, 0, x1_p, dst, N_EDGES);
    }
    // 4) e1 = relu(x[src]@wes1 + x[dst]@wed1 + e0@wee1 + be1)   (in place)
    {
        Seg a = {x, src, P[10], 256};
        Seg b = {x, dst, P[11], 256};
        Seg c = {e_p, nullptr, P[12], 64};
        gemm_kernel<64, 3, false><<<EG, 512>>>(a, b, c, P[13], 1, e_p, nullptr, N_EDGES);
    }
    // 4b) x1 = relu(x1)  (after aggregation; all later consumers use relu(x1))
    relu_kernel<<<(N_NODES * 128) / (256 * 4), 256>>>(x1_p, N_NODES * 128);
    // 5) x2 = x1 @ ws2 + bs2
    {
        Seg a = {x1_p, nullptr, P[14], 128};
        gemm_kernel<128, 1, false><<<NG, 512>>>(a, z, z, P[15], 0, x2_p, nullptr, N_NODES);
    }
    // 6) x2[dst] += x1[src] @ wmx2 + e1 @ wme2
    {
        Seg a = {x1_p, src, P[16], 128};
        Seg b = {e_p, nullptr, P[17], 64};
        gemm_kernel<128, 2, true><<<EG, 512>>>(a, b, z, nullptr, 0, x2_p, dst, N_EDGES);
    }
    // 7) e2 = relu(x1[src]@wes2 + x1[dst]@wed2 + e1@wee2 + be2)  (in place)
    {
        Seg a = {x1_p, src, P[18], 128};
        Seg b = {x1_p, dst, P[19], 128};
        Seg c = {e_p, nullptr, P[20], 64};
        gemm_kernel<64, 3, false><<<EG, 512>>>(a, b, c, P[21], 1, e_p, nullptr, N_EDGES);
    }
    // 8) out[g] = relu(x2[master_g]) @ ws3 + bs3
    master_node_kernel<<<N_GRAPHS, 256>>>(x2_p, P[22], P[23], out);
    // 9) out[g] += sum_{dst=master_g} relu(x2[src]) @ wmx3 + e2 @ wme3
    master_edge_kernel<<<N_EDGES / 256, 256>>>(x2_p, e_p, src, dst, P[24], P[25], out);
}

// round 5
// speedup vs baseline: 1.2243x; 1.2243x over previous
#include <cuda_runtime.h>
#include <cstddef>
#include <cstdint>

#define N_NODES 50000
#define N_EDGES 800000
#define N_GRAPHS 50
#define NODES_PER_GRAPH 1000

// Scratch (device globals; allocation rules forbid cudaMalloc)
__device__ float g_e[(size_t)N_EDGES * 64];     // 204.8 MB: e0 -> e1 -> e2 in place
__device__ float g_x1[(size_t)N_NODES * 128];   // 25.6 MB
__device__ float g_x2[(size_t)N_NODES * 128];   // 25.6 MB

struct Seg {
    const float* base;    // row-major [*, K]
    const int*   gather;  // nullptr = identity row index
    const float* W;       // [K, BN] row-major
    int K;
    int relu;             // apply relu to A elements when staging
};

__device__ __forceinline__ unsigned long long pack2(float v) {
    unsigned long long r;
    asm("mov.b64 %0, {%1, %1};" : "=l"(r) : "f"(v));
    return r;
}
__device__ __forceinline__ void ffma2(unsigned long long& d,
                                      unsigned long long a,
                                      unsigned long long b) {
    asm("fma.rn.f32x2 %0, %1, %2, %0;" : "+l"(d) : "l"(a), "l"(b));
}
__device__ __forceinline__ float lo2(unsigned long long v) {
    float2 f = *(float2*)&v; return f.x;
}
__device__ __forceinline__ float hi2(unsigned long long v) {
    float2 f = *(float2*)&v; return f.y;
}
__device__ __forceinline__ void cp16(uint32_t saddr, const float* g) {
    asm volatile("cp.async.cg.shared.global [%0], [%1], 16;" :: "r"(saddr), "l"(g));
}
__device__ __forceinline__ void cp_commit() {
    asm volatile("cp.async.commit_group;" ::: "memory");
}
__device__ __forceinline__ void cp_wait0() {
    asm volatile("cp.async.wait_group 0;" ::: "memory");
}

// Pipelined gather-GEMM, packed f32x2 accumulation.
// 256 threads, BM=128 rows/block, BK=32. Warp w owns rows w*16..w*16+15.
// Double-buffered smem: W via cp.async, A via 2-deep register prefetch.
template<int BN, int NSEG, bool SCATTER>
__global__ __launch_bounds__(256, 2) void gemm_kernel(
    Seg s0, Seg s1, Seg s2,
    const float* __restrict__ bias, int relu_out,
    float* __restrict__ out, const int* __restrict__ scat_idx, int M)
{
    constexpr int BM = 128, BK = 32;
    constexpr int TN = BN / 32;         // 4 (BN=128) or 2 (BN=64)
    constexpr int PR = 8;               // 8 row-pairs = 16 rows per warp
    constexpr int ASTR = BM + 4;        // 132: row start 528B, 16B aligned
    constexpr int WPASS = (BK * BN) / (256 * 4);   // cp.async passes

    extern __shared__ float smem[];
    float* As  = smem;                           // [2][BK][ASTR]
    float* Wsm = smem + 2 * BK * ASTR;           // [2][BK*BN]
    int*   ridx = (int*)(Wsm + 2 * BK * BN);     // [NSEG][BM]
    int*   sidx = ridx + NSEG * BM;              // [BM]

    Seg segs[3] = {s0, s1, s2};

    const int tid  = threadIdx.x;
    const int warp = tid >> 5;
    const int lane = tid & 31;
    const int row0 = blockIdx.x * BM;

    if (tid < BM) {
        int r = row0 + tid;
        bool ok = r < M;
        #pragma unroll
        for (int s = 0; s < NSEG; s++) {
            const int* g = segs[s].gather;
            ridx[s * BM + tid] = ok ? (g ? g[r] : r) : 0;
        }
        if (SCATTER) sidx[tid] = ok ? scat_idx[r] : 0;
    }
    __syncthreads();

    const int T0 = segs[0].K / BK;
    const int T1 = T0 + ((NSEG > 1) ? segs[1].K / BK : 0);
    const int T  = T1 + ((NSEG > 2) ? segs[2].K / BK : 0);

    const int ar_row  = tid >> 1;       // 0..127
    const int ar_half = tid & 1;        // which 16-float half of the 32-k slab

    // per-segment A base pointers (hoisted gather addressing)
    const float* abase[3];
    #pragma unroll
    for (int s = 0; s < NSEG; s++)
        abase[s] = segs[s].base + (size_t)ridx[s * BM + ar_row] * segs[s].K
                   + ar_half * 16;

    float4 af[4];

    auto map_tile = [&](int t, int& s, int& k0) {
        if (NSEG > 2 && t >= T1)      { s = 2; k0 = (t - T1) * BK; }
        else if (NSEG > 1 && t >= T0) { s = 1; k0 = (t - T0) * BK; }
        else                          { s = 0; k0 = t * BK; }
    };
    auto issueA = [&](int t) {
        int s, k0; map_tile(t, s, k0);
        const float* p = abase[s] + k0;
        #pragma unroll
        for (int q = 0; q < 4; q++) af[q] = *(const float4*)(p + q * 4);
    };
    auto storeA = [&](int t, int buf) {
        int s, k0; map_tile(t, s, k0);
        const int rl = segs[s].relu;
        float* dst = As + buf * (BK * ASTR);
        #pragma unroll
        for (int q = 0; q < 4; q++) {
            float4 v = af[q];
            if (rl) {
                v.x = fmaxf(v.x, 0.f); v.y = fmaxf(v.y, 0.f);
                v.z = fmaxf(v.z, 0.f); v.w = fmaxf(v.w, 0.f);
            }
            int kk = ar_half * 16 + q * 4;
            dst[(kk + 0) * ASTR + ar_row] = v.x;
            dst[(kk + 1) * ASTR + ar_row] = v.y;
            dst[(kk + 2) * ASTR + ar_row] = v.z;
            dst[(kk + 3) * ASTR + ar_row] = v.w;
        }
    };
    auto issueW = [&](int t, int buf) {
        int s, k0; map_tile(t, s, k0);
        const float* wp = segs[s].W + (size_t)k0 * BN;
        uint32_t sa = (uint32_t)__cvta_generic_to_shared(Wsm + buf * (BK * BN));
        #pragma unroll
        for (int ps = 0; ps < WPASS; ps++) {
            int i = tid * 4 + ps * 1024;
            cp16(sa + i * 4, wp + i);
        }
    };

    unsigned long long acc2[PR][TN];
    #pragma unroll
    for (int p = 0; p < PR; p++)
        #pragma unroll
        for (int j = 0; j < TN; j++) acc2[p][j] = 0ull;

    // prologue: stage tile 0, prefetch A of tile 1
    issueA(0); storeA(0, 0); issueW(0, 0); cp_commit();
    if (T > 1) issueA(1);
    cp_wait0();
    __syncthreads();

    for (int t = 0; t < T; t++) {
        int buf = t & 1;
        if (t + 1 < T) { issueW(t + 1, buf ^ 1); cp_commit(); storeA(t + 1, buf ^ 1); }
        if (t + 2 < T) issueA(t + 2);

        const float* as = As  + buf * (BK * ASTR);
        const float* ws = Wsm + buf * (BK * BN);
        #pragma unroll
        for (int k = 0; k < BK; k++) {
            ulonglong2 a01 = *(const ulonglong2*)(as + k * ASTR + warp * 16);
            ulonglong2 a23 = *(const ulonglong2*)(as + k * ASTR + warp * 16 + 4);
            ulonglong2 a45 = *(const ulonglong2*)(as + k * ASTR + warp * 16 + 8);
            ulonglong2 a67 = *(const ulonglong2*)(as + k * ASTR + warp * 16 + 12);
            unsigned long long ar[PR] = {a01.x, a01.y, a23.x, a23.y,
                                         a45.x, a45.y, a67.x, a67.y};
            unsigned long long bd[TN];
            if (TN == 4) {
                float4 bv = *(const float4*)(ws + k * BN + lane * 4);
                bd[0] = pack2(bv.x); bd[1] = pack2(bv.y);
                bd[2] = pack2(bv.z); bd[3] = pack2(bv.w);
            } else {
                float2 bv = *(const float2*)(ws + k * BN + lane * 2);
                bd[0] = pack2(bv.x); bd[1] = pack2(bv.y);
            }
            #pragma unroll
            for (int p = 0; p < PR; p++)
                #pragma unroll
                for (int j = 0; j < TN; j++)
                    ffma2(acc2[p][j], ar[p], bd[j]);
        }
        cp_wait0();
        __syncthreads();
    }

    // ---- epilogue (16 rows per warp) ----
    if (SCATTER) {
        #pragma unroll
        for (int h = 0; h < 16; h++) {
            int rl_ = warp * 16 + h;
            if (row0 + rl_ < M) {
                float* op = out + (size_t)sidx[rl_] * BN + lane * TN;
                int p = h >> 1, c = h & 1;
                if (TN == 4) {
                    float v0 = c ? hi2(acc2[p][0]) : lo2(acc2[p][0]);
                    float v1 = c ? hi2(acc2[p][1]) : lo2(acc2[p][1]);
                    float v2 = c ? hi2(acc2[p][2]) : lo2(acc2[p][2]);
                    float v3 = c ? hi2(acc2[p][3]) : lo2(acc2[p][3]);
                    asm volatile("red.global.add.v4.f32 [%0], {%1,%2,%3,%4};"
                                 :: "l"(op), "f"(v0), "f"(v1), "f"(v2), "f"(v3)
                                 : "memory");
                } else {
                    float v0 = c ? hi2(acc2[p][0]) : lo2(acc2[p][0]);
                    float v1 = c ? hi2(acc2[p][1]) : lo2(acc2[p][1]);
                    asm volatile("red.global.add.v2.f32 [%0], {%1,%2};"
                                 :: "l"(op), "f"(v0), "f"(v1)
                                 : "memory");
                }
            }
        }
    } else {
        float bv[TN];
        #pragma unroll
        for (int j = 0; j < TN; j++) bv[j] = bias ? bias[lane * TN + j] : 0.f;
        #pragma unroll
        for (int h = 0; h < 16; h++) {
            int r = row0 + warp * 16 + h;
            if (r < M) {
                int p = h >> 1, c = h & 1;
                if (TN == 4) {
                    float4 o;
                    o.x = (c ? hi2(acc2[p][0]) : lo2(acc2[p][0])) + bv[0];
                    o.y = (c ? hi2(acc2[p][1]) : lo2(acc2[p][1])) + bv[1];
                    o.z = (c ? hi2(acc2[p][2]) : lo2(acc2[p][2])) + bv[2];
                    o.w = (c ? hi2(acc2[p][3]) : lo2(acc2[p][3])) + bv[3];
                    if (relu_out) {
                        o.x = fmaxf(o.x, 0.f); o.y = fmaxf(o.y, 0.f);
                        o.z = fmaxf(o.z, 0.f); o.w = fmaxf(o.w, 0.f);
                    }
                    *(float4*)(out + (size_t)r * BN + lane * 4) = o;
                } else {
                    float2 o;
                    o.x = (c ? hi2(acc2[p][0]) : lo2(acc2[p][0])) + bv[0];
                    o.y = (c ? hi2(acc2[p][1]) : lo2(acc2[p][1])) + bv[1];
                    if (relu_out) { o.x = fmaxf(o.x, 0.f); o.y = fmaxf(o.y, 0.f); }
                    *(float2*)(out + (size_t)r * BN + lane * 2) = o;
                }
            }
        }
    }
}

// out[g] = relu(x2[g*1000]) @ ws3 + bs3   (50 x 256, K=128)
__global__ __launch_bounds__(256) void master_node_kernel(
    const float* __restrict__ x2, const float* __restrict__ ws3,
    const float* __restrict__ bs3, float* __restrict__ out)
{
    int g = blockIdx.x;
    int c = threadIdx.x;
    const float* xr = x2 + (size_t)g * NODES_PER_GRAPH * 128;
    float acc = bs3[c];
    #pragma unroll 8
    for (int k = 0; k < 128; k++)
        acc += fmaxf(xr[k], 0.f) * ws3[(size_t)k * 256 + c];
    out[(size_t)g * 256 + c] = acc;
}

// For edges with dst % 1000 == 0 (~800 of 800K):
// out[dst/1000] += relu(x2[src]) @ wmx3 + e2 @ wme3
__global__ __launch_bounds__(256) void master_edge_kernel(
    const float* __restrict__ x2, const float* __restrict__ e2,
    const int* __restrict__ src, const int* __restrict__ dst,
    const float* __restrict__ wmx3, const float* __restrict__ wme3,
    float* __restrict__ out)
{
    __shared__ float buf[8][192];
    int warp = threadIdx.x >> 5, lane = threadIdx.x & 31;
    int e0 = (blockIdx.x * 8 + warp) * 32;
    if (e0 >= N_EDGES) return;
    int e = e0 + lane;
    int d = dst[e];
    bool hit = (d % NODES_PER_GRAPH == 0);
    unsigned mask = __ballot_sync(0xffffffffu, hit);
    while (mask) {
        int b = __ffs(mask) - 1;
        mask &= mask - 1;
        int eh = e0 + b;
        int sh = src[eh];
        int dh = __shfl_sync(0xffffffffu, d, b);
        for (int k = lane; k < 128; k += 32)
            buf[warp][k] = fmaxf(x2[(size_t)sh * 128 + k], 0.f);
        for (int k = lane; k < 64; k += 32)
            buf[warp][128 + k] = e2[(size_t)eh * 64 + k];
        __syncwarp();
        float acc[8];
        #pragma unroll
        for (int i = 0; i < 8; i++) acc[i] = 0.f;
        for (int k = 0; k < 128; k++) {
            float a = buf[warp][k];
            const float* wr = wmx3 + (size_t)k * 256;
            #pragma unroll
            for (int i = 0; i < 8; i++) acc[i] += a * wr[lane + i * 32];
        }
        for (int k = 0; k < 64; k++) {
            float a = buf[warp][128 + k];
            const float* wr = wme3 + (size_t)k * 256;
            #pragma unroll
            for (int i = 0; i < 8; i++) acc[i] += a * wr[lane + i * 32];
        }
        float* op = out + (size_t)(dh / NODES_PER_GRAPH) * 256;
        #pragma unroll
        for (int i = 0; i < 8; i++) atomicAdd(op + lane + i * 32, acc[i]);
        __syncwarp();
    }
}

template<int BN, int NSEG, bool SCATTER>
static int smem_bytes() {
    constexpr int BM = 128, BK = 32, ASTR = BM + 4;
    return (2 * BK * ASTR + 2 * BK * BN) * 4 + NSEG * BM * 4 + BM * 4;
}

extern "C" void kernel_launch(void* const* d_in, const int* in_sizes, int n_in,
                              void* d_out, int out_size)
{
    const float* x         = (const float*)d_in[0];
    const int*   edge_idx  = (const int*)d_in[1];
    const float* edge_attr = (const float*)d_in[2];
    const float* w_proj    = (const float*)d_in[4];
    const float* b_proj    = (const float*)d_in[5];
    const float* P[30];
    for (int i = 0; i < 30 && i < n_in; i++) P[i] = (const float*)d_in[i];

    const int* src = edge_idx;
    const int* dst = edge_idx + N_EDGES;
    float* out = (float*)d_out;

    void* p;
    cudaGetSymbolAddress(&p, g_e);  float* e_p  = (float*)p;
    cudaGetSymbolAddress(&p, g_x1); float* x1_p = (float*)p;
    cudaGetSymbolAddress(&p, g_x2); float* x2_p = (float*)p;

    // opt-in to >48KB dynamic smem (idempotent; not a stream op, capture-safe)
    static bool attr_done = false;
    if (!attr_done) {
        cudaFuncSetAttribute(gemm_kernel<64, 1, false>,
            cudaFuncAttributeMaxDynamicSharedMemorySize, smem_bytes<64, 1, false>());
        cudaFuncSetAttribute(gemm_kernel<128, 1, false>,
            cudaFuncAttributeMaxDynamicSharedMemorySize, smem_bytes<128, 1, false>());
        cudaFuncSetAttribute(gemm_kernel<128, 2, true>,
            cudaFuncAttributeMaxDynamicSharedMemorySize, smem_bytes<128, 2, true>());
        cudaFuncSetAttribute(gemm_kernel<64, 3, false>,
            cudaFuncAttributeMaxDynamicSharedMemorySize, smem_bytes<64, 3, false>());
        attr_done = true;
    }

    Seg z = {nullptr, nullptr, nullptr, 0, 0};
    const int EG = N_EDGES / 128;                 // 6250 blocks
    const int NG = (N_NODES + 127) / 128;         // 391 blocks

    // 1) e0 = edge_attr @ w_proj + b_proj
    {
        Seg a = {edge_attr, nullptr, w_proj, 128, 0};
        gemm_kernel<64, 1, false><<<EG, 256, smem_bytes<64, 1, false>()>>>(
            a, z, z, b_proj, 0, e_p, nullptr, N_EDGES);
    }
    // 2) x1 = x @ ws1 + bs1
    {
        Seg a = {x, nullptr, P[6], 256, 0};
        gemm_kernel<128, 1, false><<<NG, 256, smem_bytes<128, 1, false>()>>>(
            a, z, z, P[7], 0, x1_p, nullptr, N_NODES);
    }
    // 3) x1[dst] += x[src] @ wmx1 + e0 @ wme1
    {
        Seg a = {x, src, P[8], 256, 0};
        Seg b = {e_p, nullptr, P[9], 64, 0};
        gemm_kernel<128, 2, true><<<EG, 256, smem_bytes<128, 2, true>()>>>(
            a, b, z, nullptr, 0, x1_p, dst, N_EDGES);
    }
    // 4) e1 = relu(x[src]@wes1 + x[dst]@wed1 + e0@wee1 + be1)   (in place)
    {
        Seg a = {x, src, P[10], 256, 0};
        Seg b = {x, dst, P[11], 256, 0};
        Seg c = {e_p, nullptr, P[12], 64, 0};
        gemm_kernel<64, 3, false><<<EG, 256, smem_bytes<64, 3, false>()>>>(
            a, b, c, P[13], 1, e_p, nullptr, N_EDGES);
    }
    // 5) x2 = relu(x1) @ ws2 + bs2
    {
        Seg a = {x1_p, nullptr, P[14], 128, 1};
        gemm_kernel<128, 1, false><<<NG, 256, smem_bytes<128, 1, false>()>>>(
            a, z, z, P[15], 0, x2_p, nullptr, N_NODES);
    }
    // 6) x2[dst] += relu(x1[src]) @ wmx2 + e1 @ wme2
    {
        Seg a = {x1_p, src, P[16], 128, 1};
        Seg b = {e_p, nullptr, P[17], 64, 0};
        gemm_kernel<128, 2, true><<<EG, 256, smem_bytes<128, 2, true>()>>>(
            a, b, z, nullptr, 0, x2_p, dst, N_EDGES);
    }
    // 7) e2 = relu(relu(x1[src])@wes2 + relu(x1[dst])@wed2 + e1@wee2 + be2)  (in place)
    {
        Seg a = {x1_p, src, P[18], 128, 1};
        Seg b = {x1_p, dst, P[19], 128, 1};
        Seg c = {e_p, nullptr, P[20], 64, 0};
        gemm_kernel<64, 3, false><<<EG, 256, smem_bytes<64, 3, false>()>>>(
            a, b, c, P[21], 1, e_p, nullptr, N_EDGES);
    }
    // 8) out[g] = relu(x2[master_g]) @ ws3 + bs3
    master_node_kernel<<<N_GRAPHS, 256>>>(x2_p, P[22], P[23], out);
    // 9) out[g] += sum_{dst=master_g} relu(x2[src]) @ wmx3 + e2 @ wme3
    master_edge_kernel<<<N_EDGES / 256, 256>>>(x2_p, e_p, src, dst, P[24], P[25], out);
}

// round 6
// speedup vs baseline: 1.2521x; 1.0227x over previous
#include <cuda_runtime.h>
#include <cstddef>
#include <cstdint>

#define N_NODES 50000
#define N_EDGES 800000
#define N_GRAPHS 50
#define NODES_PER_GRAPH 1000

// Scratch (device globals; allocation rules forbid cudaMalloc)
__device__ float g_e[(size_t)N_EDGES * 64];     // 204.8 MB: e0 -> e1 -> e2 in place
__device__ float g_x1[(size_t)N_NODES * 128];   // 25.6 MB
__device__ float g_x2[(size_t)N_NODES * 128];   // 25.6 MB

struct Seg {
    const float* base;    // row-major [*, K]
    const int*   gather;  // nullptr = identity row index
    const float* W;       // [K, BN] row-major
    int K;
};

__device__ __forceinline__ unsigned long long pack2(float v) {
    unsigned long long r;
    asm("mov.b64 %0, {%1, %1};" : "=l"(r) : "f"(v));
    return r;
}
__device__ __forceinline__ void ffma2(unsigned long long& d,
                                      unsigned long long a,
                                      unsigned long long b) {
    asm("fma.rn.f32x2 %0, %1, %2, %0;" : "+l"(d) : "l"(a), "l"(b));
}
__device__ __forceinline__ float sel2(unsigned long long v, int hi) {
    float2 f = *(float2*)&v; return hi ? f.y : f.x;
}
__device__ __forceinline__ void cp16(uint32_t saddr, const float* g) {
    asm volatile("cp.async.cg.shared.global [%0], [%1], 16;" :: "r"(saddr), "l"(g));
}
__device__ __forceinline__ void cp_commit() {
    asm volatile("cp.async.commit_group;" ::: "memory");
}
__device__ __forceinline__ void cp_wait0() {
    asm volatile("cp.async.wait_group 0;" ::: "memory");
}

// Pipelined gather-GEMM, packed f32x2 accumulation, 8x8 thread tile.
// 256 threads. Thread (ty,tx): rows {ty*4..+3, BM/2+ty*4..+3}, cols {tx*4..+3, BN/2+tx*4..+3}.
// Per k: 2 LDS.128 (A) + 2 LDS.128 (W) -> 32 FFMA2.
// Double-buffered smem: W via cp.async, A via 2-deep register prefetch.
template<int BM, int BN, int BK, int NSEG, bool SCATTER>
__global__ __launch_bounds__(256, 2) void gemm_kernel(
    Seg s0, Seg s1, Seg s2,
    const float* __restrict__ bias, int relu_out,
    float* __restrict__ out, const int* __restrict__ scat_idx, int M)
{
    constexpr int ASTR  = BM + 4;
    constexpr int WCOL  = BN / 64;                 // warps along cols (1 or 2)
    constexpr int WPASS = (BK * BN) / 1024;        // cp.async passes

    extern __shared__ float smem[];
    float* As   = smem;                            // [2][BK][ASTR]
    float* Wsm  = smem + 2 * BK * ASTR;            // [2][BK*BN]
    int*   ridx = (int*)(Wsm + 2 * BK * BN);       // [NSEG][BM]
    int*   sidx = ridx + NSEG * BM;                // [BM]

    Seg segs[3] = {s0, s1, s2};

    const int tid  = threadIdx.x;
    const int warp = tid >> 5;
    const int lane = tid & 31;
    const int row0 = blockIdx.x * BM;

    const int wc = warp % WCOL;
    const int wr = warp / WCOL;
    const int ty = wr * 4 + (lane >> 3);           // 0..BM/8-1
    const int tx = wc * 8 + (lane & 7);            // 0..BN/8-1

    // index staging
    for (int i = tid; i < BM; i += 256) {
        int r = row0 + i;
        bool ok = r < M;
        #pragma unroll
        for (int s = 0; s < NSEG; s++) {
            const int* g = segs[s].gather;
            ridx[s * BM + i] = ok ? (g ? g[r] : r) : 0;
        }
        if (SCATTER) sidx[i] = ok ? scat_idx[r] : 0;
    }
    __syncthreads();

    const int T0 = segs[0].K / BK;
    const int T1 = T0 + ((NSEG > 1) ? segs[1].K / BK : 0);
    const int T  = T1 + ((NSEG > 2) ? segs[2].K / BK : 0);

    // A staging map: 16 floats per thread
    const int ar_row  = (BM == 256) ? tid : (tid & (BM - 1));
    const int ar_half = (BM == 256) ? 0 : (tid >> 7);

    const float* abase[3];
    #pragma unroll
    for (int s = 0; s < NSEG; s++)
        abase[s] = segs[s].base + (size_t)ridx[s * BM + ar_row] * segs[s].K
                   + ar_half * 16;

    float4 af[4];

    auto map_tile = [&](int t, int& s, int& k0) {
        if (NSEG > 2 && t >= T1)      { s = 2; k0 = (t - T1) * BK; }
        else if (NSEG > 1 && t >= T0) { s = 1; k0 = (t - T0) * BK; }
        else                          { s = 0; k0 = t * BK; }
    };
    auto issueA = [&](int t) {
        int s, k0; map_tile(t, s, k0);
        const float* p = abase[s] + k0;
        #pragma unroll
        for (int q = 0; q < 4; q++) af[q] = *(const float4*)(p + q * 4);
    };
    auto storeA = [&](int buf) {
        float* dst = As + buf * (BK * ASTR);
        #pragma unroll
        for (int q = 0; q < 4; q++) {
            int kk = ar_half * 16 + q * 4;
            dst[(kk + 0) * ASTR + ar_row] = af[q].x;
            dst[(kk + 1) * ASTR + ar_row] = af[q].y;
            dst[(kk + 2) * ASTR + ar_row] = af[q].z;
            dst[(kk + 3) * ASTR + ar_row] = af[q].w;
        }
    };
    auto issueW = [&](int t, int buf) {
        int s, k0; map_tile(t, s, k0);
        const float* wp = segs[s].W + (size_t)k0 * BN;
        uint32_t sa = (uint32_t)__cvta_generic_to_shared(Wsm + buf * (BK * BN));
        #pragma unroll
        for (int ps = 0; ps < WPASS; ps++) {
            int i = tid * 4 + ps * 1024;
            cp16(sa + i * 4, wp + i);
        }
    };

    unsigned long long acc2[4][8];
    #pragma unroll
    for (int p = 0; p < 4; p++)
        #pragma unroll
        for (int j = 0; j < 8; j++) acc2[p][j] = 0ull;

    // prologue
    issueA(0); storeA(0); issueW(0, 0); cp_commit();
    if (T > 1) issueA(1);
    cp_wait0();
    __syncthreads();

    for (int t = 0; t < T; t++) {
        int buf = t & 1;
        if (t + 1 < T) { issueW(t + 1, buf ^ 1); cp_commit(); storeA(buf ^ 1); }
        if (t + 2 < T) issueA(t + 2);

        const float* as = As  + buf * (BK * ASTR);
        const float* ws = Wsm + buf * (BK * BN);
        #pragma unroll
        for (int k = 0; k < BK; k++) {
            ulonglong2 alo = *(const ulonglong2*)(as + k * ASTR + ty * 4);
            ulonglong2 ahi = *(const ulonglong2*)(as + k * ASTR + BM / 2 + ty * 4);
            float4 wlo = *(const float4*)(ws + k * BN + tx * 4);
            float4 whi = *(const float4*)(ws + k * BN + BN / 2 + tx * 4);
            unsigned long long ar[4] = {alo.x, alo.y, ahi.x, ahi.y};
            unsigned long long bd[8] = {
                pack2(wlo.x), pack2(wlo.y), pack2(wlo.z), pack2(wlo.w),
                pack2(whi.x), pack2(whi.y), pack2(whi.z), pack2(whi.w)};
            #pragma unroll
            for (int p = 0; p < 4; p++)
                #pragma unroll
                for (int j = 0; j < 8; j++)
                    ffma2(acc2[p][j], ar[p], bd[j]);
        }
        cp_wait0();
        __syncthreads();
    }

    // ---- epilogue: 8 rows per thread (4 lo-half, 4 hi-half) ----
    float bv[8];
    if (!SCATTER) {
        #pragma unroll
        for (int j = 0; j < 4; j++) {
            bv[j]     = bias ? bias[tx * 4 + j] : 0.f;
            bv[4 + j] = bias ? bias[BN / 2 + tx * 4 + j] : 0.f;
        }
    }
    #pragma unroll
    for (int h = 0; h < 8; h++) {
        int hh = h & 3;
        int p  = ((h >> 2) << 1) | (hh >> 1);
        int c  = hh & 1;
        int rl = (h < 4) ? (ty * 4 + hh) : (BM / 2 + ty * 4 + hh);
        if (row0 + rl < M) {
            if (SCATTER) {
                float* op = out + (size_t)sidx[rl] * BN;
                float v0 = sel2(acc2[p][0], c), v1 = sel2(acc2[p][1], c);
                float v2 = sel2(acc2[p][2], c), v3 = sel2(acc2[p][3], c);
                asm volatile("red.global.add.v4.f32 [%0], {%1,%2,%3,%4};"
                             :: "l"(op + tx * 4), "f"(v0), "f"(v1), "f"(v2), "f"(v3)
                             : "memory");
                float u0 = sel2(acc2[p][4], c), u1 = sel2(acc2[p][5], c);
                float u2 = sel2(acc2[p][6], c), u3 = sel2(acc2[p][7], c);
                asm volatile("red.global.add.v4.f32 [%0], {%1,%2,%3,%4};"
                             :: "l"(op + BN / 2 + tx * 4), "f"(u0), "f"(u1), "f"(u2), "f"(u3)
                             : "memory");
            } else {
                float* op = out + (size_t)(row0 + rl) * BN;
                float4 o0, o1;
                o0.x = sel2(acc2[p][0], c) + bv[0];
                o0.y = sel2(acc2[p][1], c) + bv[1];
                o0.z = sel2(acc2[p][2], c) + bv[2];
                o0.w = sel2(acc2[p][3], c) + bv[3];
                o1.x = sel2(acc2[p][4], c) + bv[4];
                o1.y = sel2(acc2[p][5], c) + bv[5];
                o1.z = sel2(acc2[p][6], c) + bv[6];
                o1.w = sel2(acc2[p][7], c) + bv[7];
                if (relu_out) {
                    o0.x = fmaxf(o0.x, 0.f); o0.y = fmaxf(o0.y, 0.f);
                    o0.z = fmaxf(o0.z, 0.f); o0.w = fmaxf(o0.w, 0.f);
                    o1.x = fmaxf(o1.x, 0.f); o1.y = fmaxf(o1.y, 0.f);
                    o1.z = fmaxf(o1.z, 0.f); o1.w = fmaxf(o1.w, 0.f);
                }
                *(float4*)(op + tx * 4) = o0;
                *(float4*)(op + BN / 2 + tx * 4) = o1;
            }
        }
    }
}

// in-place relu over n floats (n % 1024 == 0)
__global__ __launch_bounds__(256) void relu_kernel(float* __restrict__ p, int n)
{
    int i = (blockIdx.x * 256 + threadIdx.x) * 4;
    if (i < n) {
        float4 v = *(float4*)(p + i);
        v.x = fmaxf(v.x, 0.f); v.y = fmaxf(v.y, 0.f);
        v.z = fmaxf(v.z, 0.f); v.w = fmaxf(v.w, 0.f);
        *(float4*)(p + i) = v;
    }
}

// out[g] = relu(x2[g*1000]) @ ws3 + bs3   (50 x 256, K=128)
__global__ __launch_bounds__(256) void master_node_kernel(
    const float* __restrict__ x2, const float* __restrict__ ws3,
    const float* __restrict__ bs3, float* __restrict__ out)
{
    int g = blockIdx.x;
    int c = threadIdx.x;
    const float* xr = x2 + (size_t)g * NODES_PER_GRAPH * 128;
    float acc = bs3[c];
    #pragma unroll 8
    for (int k = 0; k < 128; k++)
        acc += fmaxf(xr[k], 0.f) * ws3[(size_t)k * 256 + c];
    out[(size_t)g * 256 + c] = acc;
}

// For edges with dst % 1000 == 0 (~800 of 800K):
// out[dst/1000] += relu(x2[src]) @ wmx3 + e2 @ wme3
__global__ __launch_bounds__(256) void master_edge_kernel(
    const float* __restrict__ x2, const float* __restrict__ e2,
    const int* __restrict__ src, const int* __restrict__ dst,
    const float* __restrict__ wmx3, const float* __restrict__ wme3,
    float* __restrict__ out)
{
    __shared__ float buf[8][192];
    int warp = threadIdx.x >> 5, lane = threadIdx.x & 31;
    int e0 = (blockIdx.x * 8 + warp) * 32;
    if (e0 >= N_EDGES) return;
    int e = e0 + lane;
    int d = dst[e];
    bool hit = (d % NODES_PER_GRAPH == 0);
    unsigned mask = __ballot_sync(0xffffffffu, hit);
    while (mask) {
        int b = __ffs(mask) - 1;
        mask &= mask - 1;
        int eh = e0 + b;
        int sh = src[eh];
        int dh = __shfl_sync(0xffffffffu, d, b);
        for (int k = lane; k < 128; k += 32)
            buf[warp][k] = fmaxf(x2[(size_t)sh * 128 + k], 0.f);
        for (int k = lane; k < 64; k += 32)
            buf[warp][128 + k] = e2[(size_t)eh * 64 + k];
        __syncwarp();
        float acc[8];
        #pragma unroll
        for (int i = 0; i < 8; i++) acc[i] = 0.f;
        for (int k = 0; k < 128; k++) {
            float a = buf[warp][k];
            const float* wr = wmx3 + (size_t)k * 256;
            #pragma unroll
            for (int i = 0; i < 8; i++) acc[i] += a * wr[lane + i * 32];
        }
        for (int k = 0; k < 64; k++) {
            float a = buf[warp][128 + k];
            const float* wr = wme3 + (size_t)k * 256;
            #pragma unroll
            for (int i = 0; i < 8; i++) acc[i] += a * wr[lane + i * 32];
        }
        float* op = out + (size_t)(dh / NODES_PER_GRAPH) * 256;
        #pragma unroll
        for (int i = 0; i < 8; i++) atomicAdd(op + lane + i * 32, acc[i]);
        __syncwarp();
    }
}

template<int BM, int BN, int BK, int NSEG>
static int smem_bytes() {
    constexpr int ASTR = BM + 4;
    return (2 * BK * ASTR + 2 * BK * BN) * 4 + NSEG * BM * 4 + BM * 4;
}

extern "C" void kernel_launch(void* const* d_in, const int* in_sizes, int n_in,
                              void* d_out, int out_size)
{
    const float* x         = (const float*)d_in[0];
    const int*   edge_idx  = (const int*)d_in[1];
    const float* edge_attr = (const float*)d_in[2];
    const float* w_proj    = (const float*)d_in[4];
    const float* b_proj    = (const float*)d_in[5];
    const float* P[30];
    for (int i = 0; i < 30 && i < n_in; i++) P[i] = (const float*)d_in[i];

    const int* src = edge_idx;
    const int* dst = edge_idx + N_EDGES;
    float* out = (float*)d_out;

    void* p;
    cudaGetSymbolAddress(&p, g_e);  float* e_p  = (float*)p;
    cudaGetSymbolAddress(&p, g_x1); float* x1_p = (float*)p;
    cudaGetSymbolAddress(&p, g_x2); float* x2_p = (float*)p;

    static bool attr_done = false;
    if (!attr_done) {
        cudaFuncSetAttribute(gemm_kernel<256, 64, 16, 1, false>,
            cudaFuncAttributeMaxDynamicSharedMemorySize, smem_bytes<256, 64, 16, 1>());
        cudaFuncSetAttribute(gemm_kernel<128, 128, 32, 1, false>,
            cudaFuncAttributeMaxDynamicSharedMemorySize, smem_bytes<128, 128, 32, 1>());
        cudaFuncSetAttribute(gemm_kernel<128, 128, 32, 2, true>,
            cudaFuncAttributeMaxDynamicSharedMemorySize, smem_bytes<128, 128, 32, 2>());
        cudaFuncSetAttribute(gemm_kernel<256, 64, 16, 3, false>,
            cudaFuncAttributeMaxDynamicSharedMemorySize, smem_bytes<256, 64, 16, 3>());
        attr_done = true;
    }

    Seg z = {nullptr, nullptr, nullptr, 0};
    const int EG64  = N_EDGES / 256;              // 3125 blocks (BM=256)
    const int EG128 = N_EDGES / 128;              // 6250 blocks (BM=128)
    const int NG    = (N_NODES + 127) / 128;      // 391 blocks

    // 1) e0 = edge_attr @ w_proj + b_proj
    {
        Seg a = {edge_attr, nullptr, w_proj, 128};
        gemm_kernel<256, 64, 16, 1, false><<<EG64, 256, smem_bytes<256, 64, 16, 1>()>>>(
            a, z, z, b_proj, 0, e_p, nullptr, N_EDGES);
    }
    // 2) x1 = x @ ws1 + bs1
    {
        Seg a = {x, nullptr, P[6], 256};
        gemm_kernel<128, 128, 32, 1, false><<<NG, 256, smem_bytes<128, 128, 32, 1>()>>>(
            a, z, z, P[7], 0, x1_p, nullptr, N_NODES);
    }
    // 3) x1[dst] += x[src] @ wmx1 + e0 @ wme1
    {
        Seg a = {x, src, P[8], 256};
        Seg b = {e_p, nullptr, P[9], 64};
        gemm_kernel<128, 128, 32, 2, true><<<EG128, 256, smem_bytes<128, 128, 32, 2>()>>>(
            a, b, z, nullptr, 0, x1_p, dst, N_EDGES);
    }
    // 4) e1 = relu(x[src]@wes1 + x[dst]@wed1 + e0@wee1 + be1)   (in place)
    {
        Seg a = {x, src, P[10], 256};
        Seg b = {x, dst, P[11], 256};
        Seg c = {e_p, nullptr, P[12], 64};
        gemm_kernel<256, 64, 16, 3, false><<<EG64, 256, smem_bytes<256, 64, 16, 3>()>>>(
            a, b, c, P[13], 1, e_p, nullptr, N_EDGES);
    }
    // 4b) x1 = relu(x1)  (after aggregation; all later consumers use relu(x1))
    relu_kernel<<<(N_NODES * 128) / 1024, 256>>>(x1_p, N_NODES * 128);
    // 5) x2 = x1 @ ws2 + bs2
    {
        Seg a = {x1_p, nullptr, P[14], 128};
        gemm_kernel<128, 128, 32, 1, false><<<NG, 256, smem_bytes<128, 128, 32, 1>()>>>(
            a, z, z, P[15], 0, x2_p, nullptr, N_NODES);
    }
    // 6) x2[dst] += x1[src] @ wmx2 + e1 @ wme2
    {
        Seg a = {x1_p, src, P[16], 128};
        Seg b = {e_p, nullptr, P[17], 64};
        gemm_kernel<128, 128, 32, 2, true><<<EG128, 256, smem_bytes<128, 128, 32, 2>()>>>(
            a, b, z, nullptr, 0, x2_p, dst, N_EDGES);
    }
    // 7) e2 = relu(x1[src]@wes2 + x1[dst]@wed2 + e1@wee2 + be2)  (in place)
    {
        Seg a = {x1_p, src, P[18], 128};
        Seg b = {x1_p, dst, P[19], 128};
        Seg c = {e_p, nullptr, P[20], 64};
        gemm_kernel<256, 64, 16, 3, false><<<EG64, 256, smem_bytes<256, 64, 16, 3>()>>>(
            a, b, c, P[21], 1, e_p, nullptr, N_EDGES);
    }
    // 8) out[g] = relu(x2[master_g]) @ ws3 + bs3
    master_node_kernel<<<N_GRAPHS, 256>>>(x2_p, P[22], P[23], out);
    // 9) out[g] += sum_{dst=master_g} relu(x2[src]) @ wmx3 + e2 @ wme3
    master_edge_kernel<<<N_EDGES / 256, 256>>>(x2_p, e_p, src, dst, P[24], P[25], out);
}

// round 7
// speedup vs baseline: 7.2458x; 5.7867x over previous
#include <cuda_runtime.h>
#include <cstddef>
#include <cstdint>

#define N_NODES 50000
#define N_EDGES 800000
#define N_GRAPHS 50
#define NODES_PER_GRAPH 1000

#define CAP_L1 327680     // edges needing layer-1 message (expected ~224K)
#define CAP_L2 32768      // edges needing e1/layer-2 message (expected ~13.4K)
#define CAP_N2 4096       // nodes needing x2 (expected ~850)

// Scratch (device globals; allocation rules forbid cudaMalloc)
__device__ float g_e[(size_t)N_EDGES * 64];     // e0 -> e1 -> e2 in place (sparse rows)
__device__ float g_x1[(size_t)N_NODES * 128];
__device__ float g_x2[(size_t)N_NODES * 128];

__device__ int d_flag1[N_NODES];   // x1 needed
__device__ int d_flag2[N_NODES];   // x2 needed
__device__ int d_list1[CAP_L1];
__device__ int d_list2[CAP_L2];
__device__ int d_nlist1[N_NODES];
__device__ int d_nlist2[CAP_N2];
__device__ int d_cnt[4];           // 0:n2 1:l2 2:l1 3:n1

struct Seg {
    const float* base;    // row-major [*, K]
    const int*   gather;  // applied to row id from rowlist; nullptr = id itself
    const float* W;       // [K, BN] row-major
    int K;
};

__device__ __forceinline__ unsigned long long pack2(float v) {
    unsigned long long r;
    asm("mov.b64 %0, {%1, %1};" : "=l"(r) : "f"(v));
    return r;
}
__device__ __forceinline__ void ffma2(unsigned long long& d,
                                      unsigned long long a,
                                      unsigned long long b) {
    asm("fma.rn.f32x2 %0, %1, %2, %0;" : "+l"(d) : "l"(a), "l"(b));
}
__device__ __forceinline__ float sel2(unsigned long long v, int hi) {
    float2 f = *(float2*)&v; return hi ? f.y : f.x;
}
__device__ __forceinline__ void cp16(uint32_t saddr, const float* g) {
    asm volatile("cp.async.cg.shared.global [%0], [%1], 16;" :: "r"(saddr), "l"(g));
}
__device__ __forceinline__ void cp_commit() {
    asm volatile("cp.async.commit_group;" ::: "memory");
}
__device__ __forceinline__ void cp_wait0() {
    asm volatile("cp.async.wait_group 0;" ::: "memory");
}

// ---------------- frontier marking / compaction ----------------

__global__ __launch_bounds__(256) void zero_kernel()
{
    int i = blockIdx.x * 256 + threadIdx.x;
    for (int v = i; v < N_NODES; v += gridDim.x * 256) {
        d_flag1[v] = 0; d_flag2[v] = 0;
    }
    if (i < 4) d_cnt[i] = 0;
}

// flag2: masters + sources of master edges (nodes whose x2 is read by layer 3)
__global__ __launch_bounds__(256) void mark2_kernel(
    const int* __restrict__ src, const int* __restrict__ dst)
{
    int e = blockIdx.x * 256 + threadIdx.x;
    if (e < N_EDGES && dst[e] % NODES_PER_GRAPH == 0)
        d_flag2[src[e]] = 1;
    if (blockIdx.x == 0 && threadIdx.x < N_GRAPHS)
        d_flag2[threadIdx.x * NODES_PER_GRAPH] = 1;
}

// compact flag2 nodes -> nlist2; flag2 subset of flag1
__global__ __launch_bounds__(256) void nodes2_kernel()
{
    int v = blockIdx.x * 256 + threadIdx.x;
    if (v < N_NODES && d_flag2[v]) {
        d_flag1[v] = 1;
        int i = atomicAdd(&d_cnt[0], 1);
        d_nlist2[i] = v;
    }
}

// list2: edges into flag2 nodes (need e1 + layer-2 message); their srcs need x1
__global__ __launch_bounds__(256) void list2_kernel(
    const int* __restrict__ src, const int* __restrict__ dst)
{
    int e = blockIdx.x * 256 + threadIdx.x;
    if (e < N_EDGES && d_flag2[dst[e]]) {
        int i = atomicAdd(&d_cnt[1], 1);
        d_list2[i] = e;
        d_flag1[src[e]] = 1;
    }
}

// list1: edges into flag1 nodes (need e0 + layer-1 message). list2 subset of list1.
__global__ __launch_bounds__(256) void list1_kernel(const int* __restrict__ dst)
{
    int e = blockIdx.x * 256 + threadIdx.x;
    if (e < N_EDGES && d_flag1[dst[e]]) {
        int i = atomicAdd(&d_cnt[2], 1);
        d_list1[i] = e;
    }
}

__global__ __launch_bounds__(256) void nodes1_kernel()
{
    int v = blockIdx.x * 256 + threadIdx.x;
    if (v < N_NODES && d_flag1[v]) {
        int i = atomicAdd(&d_cnt[3], 1);
        d_nlist1[i] = v;
    }
}

// in-place relu of g_x1 rows listed in nlist1 (128 floats per row)
__global__ __launch_bounds__(256) void relu_rows_kernel(float* __restrict__ x1)
{
    int n = d_cnt[3];
    int total = n * 32;                // 32 float4 per row
    for (int i = blockIdx.x * 256 + threadIdx.x; i < total; i += gridDim.x * 256) {
        int r = i >> 5, c = i & 31;
        float4* p = (float4*)(x1 + (size_t)d_nlist1[r] * 128) + c;
        float4 v = *p;
        v.x = fmaxf(v.x, 0.f); v.y = fmaxf(v.y, 0.f);
        v.z = fmaxf(v.z, 0.f); v.w = fmaxf(v.w, 0.f);
        *p = v;
    }
}

// ---------------- pipelined gather-GEMM (f32x2 FMA, 8x8 thread tile) ----------------
// 256 threads. Rows come from rowlist[row0..row0+BM); per-seg gather applied on top.
// OUT=1: plain store at scat row (scat_map applied to row id, nullptr = id itself).
// OUT=2: red.global.add at scat row.
template<int BM, int BN, int BK, int NSEG, int OUT>
__global__ __launch_bounds__(256, 2) void gemm_kernel(
    Seg s0, Seg s1, Seg s2,
    const float* __restrict__ bias, int relu_out,
    float* __restrict__ out,
    const int* __restrict__ rowlist,
    const int* __restrict__ scat_map,
    const int* __restrict__ Mptr)
{
    constexpr int ASTR  = BM + 4;
    constexpr int WCOL  = BN / 64;
    constexpr int WPASS = (BK * BN) / 1024;

    const int M    = *Mptr;
    const int row0 = blockIdx.x * BM;
    if (row0 >= M) return;

    extern __shared__ float smem[];
    float* As   = smem;                            // [2][BK][ASTR]
    float* Wsm  = smem + 2 * BK * ASTR;            // [2][BK*BN]
    int*   ridx = (int*)(Wsm + 2 * BK * BN);       // [NSEG][BM]
    int*   sidx = ridx + NSEG * BM;                // [BM]

    Seg segs[3] = {s0, s1, s2};

    const int tid  = threadIdx.x;
    const int warp = tid >> 5;
    const int lane = tid & 31;

    const int wc = warp % WCOL;
    const int wr = warp / WCOL;
    const int ty = wr * 4 + (lane >> 3);
    const int tx = wc * 8 + (lane & 7);

    for (int i = tid; i < BM; i += 256) {
        int r = row0 + i;
        int rid = rowlist[(r < M) ? r : row0];     // pad with a valid row
        #pragma unroll
        for (int s = 0; s < NSEG; s++) {
            const int* g = segs[s].gather;
            ridx[s * BM + i] = g ? g[rid] : rid;
        }
        sidx[i] = scat_map ? scat_map[rid] : rid;
    }
    __syncthreads();

    const int T0 = segs[0].K / BK;
    const int T1 = T0 + ((NSEG > 1) ? segs[1].K / BK : 0);
    const int T  = T1 + ((NSEG > 2) ? segs[2].K / BK : 0);

    const int ar_row  = (BM == 256) ? tid : (tid & (BM - 1));
    const int ar_half = (BM == 256) ? 0 : (tid >> 7);

    const float* abase[3];
    #pragma unroll
    for (int s = 0; s < NSEG; s++)
        abase[s] = segs[s].base + (size_t)ridx[s * BM + ar_row] * segs[s].K
                   + ar_half * 16;

    float4 af[4];

    auto map_tile = [&](int t, int& s, int& k0) {
        if (NSEG > 2 && t >= T1)      { s = 2; k0 = (t - T1) * BK; }
        else if (NSEG > 1 && t >= T0) { s = 1; k0 = (t - T0) * BK; }
        else                          { s = 0; k0 = t * BK; }
    };
    auto issueA = [&](int t) {
        int s, k0; map_tile(t, s, k0);
        const float* p = abase[s] + k0;
        #pragma unroll
        for (int q = 0; q < 4; q++) af[q] = *(const float4*)(p + q * 4);
    };
    auto storeA = [&](int buf) {
        float* dst = As + buf * (BK * ASTR);
        #pragma unroll
        for (int q = 0; q < 4; q++) {
            int kk = ar_half * 16 + q * 4;
            dst[(kk + 0) * ASTR + ar_row] = af[q].x;
            dst[(kk + 1) * ASTR + ar_row] = af[q].y;
            dst[(kk + 2) * ASTR + ar_row] = af[q].z;
            dst[(kk + 3) * ASTR + ar_row] = af[q].w;
        }
    };
    auto issueW = [&](int t, int buf) {
        int s, k0; map_tile(t, s, k0);
        const float* wp = segs[s].W + (size_t)k0 * BN;
        uint32_t sa = (uint32_t)__cvta_generic_to_shared(Wsm + buf * (BK * BN));
        #pragma unroll
        for (int ps = 0; ps < WPASS; ps++) {
            int i = tid * 4 + ps * 1024;
            cp16(sa + i * 4, wp + i);
        }
    };

    unsigned long long acc2[4][8];
    #pragma unroll
    for (int p = 0; p < 4; p++)
        #pragma unroll
        for (int j = 0; j < 8; j++) acc2[p][j] = 0ull;

    issueA(0); storeA(0); issueW(0, 0); cp_commit();
    if (T > 1) issueA(1);
    cp_wait0();
    __syncthreads();

    for (int t = 0; t < T; t++) {
        int buf = t & 1;
        if (t + 1 < T) { issueW(t + 1, buf ^ 1); cp_commit(); storeA(buf ^ 1); }
        if (t + 2 < T) issueA(t + 2);

        const float* as = As  + buf * (BK * ASTR);
        const float* ws = Wsm + buf * (BK * BN);
        #pragma unroll
        for (int k = 0; k < BK; k++) {
            ulonglong2 alo = *(const ulonglong2*)(as + k * ASTR + ty * 4);
            ulonglong2 ahi = *(const ulonglong2*)(as + k * ASTR + BM / 2 + ty * 4);
            float4 wlo = *(const float4*)(ws + k * BN + tx * 4);
            float4 whi = *(const float4*)(ws + k * BN + BN / 2 + tx * 4);
            unsigned long long ar[4] = {alo.x, alo.y, ahi.x, ahi.y};
            unsigned long long bd[8] = {
                pack2(wlo.x), pack2(wlo.y), pack2(wlo.z), pack2(wlo.w),
                pack2(whi.x), pack2(whi.y), pack2(whi.z), pack2(whi.w)};
            #pragma unroll
            for (int p = 0; p < 4; p++)
                #pragma unroll
                for (int j = 0; j < 8; j++)
                    ffma2(acc2[p][j], ar[p], bd[j]);
        }
        cp_wait0();
        __syncthreads();
    }

    // ---- epilogue: 8 rows per thread ----
    float bv[8];
    if (OUT == 1) {
        #pragma unroll
        for (int j = 0; j < 4; j++) {
            bv[j]     = bias ? bias[tx * 4 + j] : 0.f;
            bv[4 + j] = bias ? bias[BN / 2 + tx * 4 + j] : 0.f;
        }
    }
    #pragma unroll
    for (int h = 0; h < 8; h++) {
        int hh = h & 3;
        int p  = ((h >> 2) << 1) | (hh >> 1);
        int c  = hh & 1;
        int rl = (h < 4) ? (ty * 4 + hh) : (BM / 2 + ty * 4 + hh);
        if (row0 + rl < M) {
            float* op = out + (size_t)sidx[rl] * BN;
            if (OUT == 2) {
                float v0 = sel2(acc2[p][0], c), v1 = sel2(acc2[p][1], c);
                float v2 = sel2(acc2[p][2], c), v3 = sel2(acc2[p][3], c);
                asm volatile("red.global.add.v4.f32 [%0], {%1,%2,%3,%4};"
                             :: "l"(op + tx * 4), "f"(v0), "f"(v1), "f"(v2), "f"(v3)
                             : "memory");
                float u0 = sel2(acc2[p][4], c), u1 = sel2(acc2[p][5], c);
                float u2 = sel2(acc2[p][6], c), u3 = sel2(acc2[p][7], c);
                asm volatile("red.global.add.v4.f32 [%0], {%1,%2,%3,%4};"
                             :: "l"(op + BN / 2 + tx * 4), "f"(u0), "f"(u1), "f"(u2), "f"(u3)
                             : "memory");
            } else {
                float4 o0, o1;
                o0.x = sel2(acc2[p][0], c) + bv[0];
                o0.y = sel2(acc2[p][1], c) + bv[1];
                o0.z = sel2(acc2[p][2], c) + bv[2];
                o0.w = sel2(acc2[p][3], c) + bv[3];
                o1.x = sel2(acc2[p][4], c) + bv[4];
                o1.y = sel2(acc2[p][5], c) + bv[5];
                o1.z = sel2(acc2[p][6], c) + bv[6];
                o1.w = sel2(acc2[p][7], c) + bv[7];
                if (relu_out) {
                    o0.x = fmaxf(o0.x, 0.f); o0.y = fmaxf(o0.y, 0.f);
                    o0.z = fmaxf(o0.z, 0.f); o0.w = fmaxf(o0.w, 0.f);
                    o1.x = fmaxf(o1.x, 0.f); o1.y = fmaxf(o1.y, 0.f);
                    o1.z = fmaxf(o1.z, 0.f); o1.w = fmaxf(o1.w, 0.f);
                }
                *(float4*)(op + tx * 4) = o0;
                *(float4*)(op + BN / 2 + tx * 4) = o1;
            }
        }
    }
}

// ---------------- layer-3 master kernels ----------------

__global__ __launch_bounds__(256) void master_node_kernel(
    const float* __restrict__ x2, const float* __restrict__ ws3,
    const float* __restrict__ bs3, float* __restrict__ out)
{
    int g = blockIdx.x;
    int c = threadIdx.x;
    const float* xr = x2 + (size_t)g * NODES_PER_GRAPH * 128;
    float acc = bs3[c];
    #pragma unroll 8
    for (int k = 0; k < 128; k++)
        acc += fmaxf(xr[k], 0.f) * ws3[(size_t)k * 256 + c];
    out[(size_t)g * 256 + c] = acc;
}

__global__ __launch_bounds__(256) void master_edge_kernel(
    const float* __restrict__ x2, const float* __restrict__ e2,
    const int* __restrict__ src, const int* __restrict__ dst,
    const float* __restrict__ wmx3, const float* __restrict__ wme3,
    float* __restrict__ out)
{
    __shared__ float buf[8][192];
    int warp = threadIdx.x >> 5, lane = threadIdx.x & 31;
    int e0 = (blockIdx.x * 8 + warp) * 32;
    if (e0 >= N_EDGES) return;
    int e = e0 + lane;
    int d = dst[e];
    bool hit = (d % NODES_PER_GRAPH == 0);
    unsigned mask = __ballot_sync(0xffffffffu, hit);
    while (mask) {
        int b = __ffs(mask) - 1;
        mask &= mask - 1;
        int eh = e0 + b;
        int sh = src[eh];
        int dh = __shfl_sync(0xffffffffu, d, b);
        for (int k = lane; k < 128; k += 32)
            buf[warp][k] = fmaxf(x2[(size_t)sh * 128 + k], 0.f);
        for (int k = lane; k < 64; k += 32)
            buf[warp][128 + k] = e2[(size_t)eh * 64 + k];
        __syncwarp();
        float acc[8];
        #pragma unroll
        for (int i = 0; i < 8; i++) acc[i] = 0.f;
        for (int k = 0; k < 128; k++) {
            float a = buf[warp][k];
            const float* wr = wmx3 + (size_t)k * 256;
            #pragma unroll
            for (int i = 0; i < 8; i++) acc[i] += a * wr[lane + i * 32];
        }
        for (int k = 0; k < 64; k++) {
            float a = buf[warp][128 + k];
            const float* wr = wme3 + (size_t)k * 256;
            #pragma unroll
            for (int i = 0; i < 8; i++) acc[i] += a * wr[lane + i * 32];
        }
        float* op = out + (size_t)(dh / NODES_PER_GRAPH) * 256;
        #pragma unroll
        for (int i = 0; i < 8; i++) atomicAdd(op + lane + i * 32, acc[i]);
        __syncwarp();
    }
}

template<int BM, int BN, int BK, int NSEG>
static int smem_bytes() {
    constexpr int ASTR = BM + 4;
    return (2 * BK * ASTR + 2 * BK * BN) * 4 + NSEG * BM * 4 + BM * 4;
}

extern "C" void kernel_launch(void* const* d_in, const int* in_sizes, int n_in,
                              void* d_out, int out_size)
{
    const float* x         = (const float*)d_in[0];
    const int*   edge_idx  = (const int*)d_in[1];
    const float* edge_attr = (const float*)d_in[2];
    const float* w_proj    = (const float*)d_in[4];
    const float* b_proj    = (const float*)d_in[5];
    const float* P[30];
    for (int i = 0; i < 30 && i < n_in; i++) P[i] = (const float*)d_in[i];

    const int* src = edge_idx;
    const int* dst = edge_idx + N_EDGES;
    float* out = (float*)d_out;

    void* p;
    cudaGetSymbolAddress(&p, g_e);      float* e_p  = (float*)p;
    cudaGetSymbolAddress(&p, g_x1);     float* x1_p = (float*)p;
    cudaGetSymbolAddress(&p, g_x2);     float* x2_p = (float*)p;
    cudaGetSymbolAddress(&p, d_list1);  const int* l1 = (const int*)p;
    cudaGetSymbolAddress(&p, d_list2);  const int* l2 = (const int*)p;
    cudaGetSymbolAddress(&p, d_nlist1); const int* n1 = (const int*)p;
    cudaGetSymbolAddress(&p, d_nlist2); const int* n2 = (const int*)p;
    cudaGetSymbolAddress(&p, d_cnt);    const int* cnt = (const int*)p;
    const int* c_n2 = cnt + 0;
    const int* c_l2 = cnt + 1;
    const int* c_l1 = cnt + 2;
    const int* c_n1 = cnt + 3;

    static bool attr_done = false;
    if (!attr_done) {
        cudaFuncSetAttribute(gemm_kernel<256, 64, 16, 1, 1>,
            cudaFuncAttributeMaxDynamicSharedMemorySize, smem_bytes<256, 64, 16, 1>());
        cudaFuncSetAttribute(gemm_kernel<128, 128, 32, 1, 1>,
            cudaFuncAttributeMaxDynamicSharedMemorySize, smem_bytes<128, 128, 32, 1>());
        cudaFuncSetAttribute(gemm_kernel<128, 128, 32, 2, 2>,
            cudaFuncAttributeMaxDynamicSharedMemorySize, smem_bytes<128, 128, 32, 2>());
        cudaFuncSetAttribute(gemm_kernel<256, 64, 16, 3, 1>,
            cudaFuncAttributeMaxDynamicSharedMemorySize, smem_bytes<256, 64, 16, 3>());
        attr_done = true;
    }

    Seg z = {nullptr, nullptr, nullptr, 0};
    const int EGRID = (N_EDGES + 255) / 256;      // 3125
    const int NGRID = (N_NODES + 255) / 256;      // 196

    // ---- frontier marking ----
    zero_kernel<<<NGRID, 256>>>();
    mark2_kernel<<<EGRID, 256>>>(src, dst);
    nodes2_kernel<<<NGRID, 256>>>();
    list2_kernel<<<EGRID, 256>>>(src, dst);
    list1_kernel<<<EGRID, 256>>>(dst);
    nodes1_kernel<<<NGRID, 256>>>();

    // ---- pruned compute ----
    // e0 = edge_attr @ w_proj + b_proj, edges in list1 (list2 is a subset)
    {
        Seg a = {edge_attr, nullptr, w_proj, 128};
        gemm_kernel<256, 64, 16, 1, 1><<<CAP_L1 / 256, 256, smem_bytes<256, 64, 16, 1>()>>>(
            a, z, z, b_proj, 0, e_p, l1, nullptr, c_l1);
    }
    // x1[v] = x[v] @ ws1 + bs1, nodes in nlist1 (scatter-store)
    {
        Seg a = {x, nullptr, P[6], 256};
        gemm_kernel<128, 128, 32, 1, 1><<<(N_NODES + 127) / 128, 256, smem_bytes<128, 128, 32, 1>()>>>(
            a, z, z, P[7], 0, x1_p, n1, nullptr, c_n1);
    }
    // x1[dst] += x[src] @ wmx1 + e0 @ wme1, edges in list1
    {
        Seg a = {x, src, P[8], 256};
        Seg b = {e_p, nullptr, P[9], 64};
        gemm_kernel<128, 128, 32, 2, 2><<<CAP_L1 / 128, 256, smem_bytes<128, 128, 32, 2>()>>>(
            a, b, z, nullptr, 0, x1_p, l1, dst, c_l1);
    }
    // x1 = relu(x1) on nlist1 rows
    relu_rows_kernel<<<400, 256>>>(x1_p);
    // e1 = relu(x[src]@wes1 + x[dst]@wed1 + e0@wee1 + be1), edges in list2 (in place)
    {
        Seg a = {x, src, P[10], 256};
        Seg b = {x, dst, P[11], 256};
        Seg c = {e_p, nullptr, P[12], 64};
        gemm_kernel<256, 64, 16, 3, 1><<<CAP_L2 / 256, 256, smem_bytes<256, 64, 16, 3>()>>>(
            a, b, c, P[13], 1, e_p, l2, nullptr, c_l2);
    }
    // x2[v] = relu_x1[v] @ ws2 + bs2, nodes in nlist2
    {
        Seg a = {x1_p, nullptr, P[14], 128};
        gemm_kernel<128, 128, 32, 1, 1><<<CAP_N2 / 128, 256, smem_bytes<128, 128, 32, 1>()>>>(
            a, z, z, P[15], 0, x2_p, n2, nullptr, c_n2);
    }
    // x2[dst] += relu_x1[src] @ wmx2 + e1 @ wme2, edges in list2
    {
        Seg a = {x1_p, src, P[16], 128};
        Seg b = {e_p, nullptr, P[17], 64};
        gemm_kernel<128, 128, 32, 2, 2><<<CAP_L2 / 128, 256, smem_bytes<128, 128, 32, 2>()>>>(
            a, b, z, nullptr, 0, x2_p, l2, dst, c_l2);
    }
    // e2 = relu(relu_x1[src]@wes2 + relu_x1[dst]@wed2 + e1@wee2 + be2), edges in list2 (in place)
    {
        Seg a = {x1_p, src, P[18], 128};
        Seg b = {x1_p, dst, P[19], 128};
        Seg c = {e_p, nullptr, P[20], 64};
        gemm_kernel<256, 64, 16, 3, 1><<<CAP_L2 / 256, 256, smem_bytes<256, 64, 16, 3>()>>>(
            a, b, c, P[21], 1, e_p, l2, nullptr, c_l2);
    }
    // out[g] = relu(x2[master_g]) @ ws3 + bs3
    master_node_kernel<<<N_GRAPHS, 256>>>(x2_p, P[22], P[23], out);
    // out[g] += sum_{dst=master_g} relu(x2[src]) @ wmx3 + e2 @ wme3
    master_edge_kernel<<<N_EDGES / 256, 256>>>(x2_p, e_p, src, dst, P[24], P[25], out);
}

// round 8
// speedup vs baseline: 12.1700x; 1.6796x over previous
#include <cuda_runtime.h>
#include <cstddef>
#include <cstdint>

#define N_NODES 50000
#define N_EDGES 800000
#define N_GRAPHS 50
#define NODES_PER_GRAPH 1000

#define CAP_L2 32768      // edges into flag2 nodes (expected ~13.4K)
#define CAP_L3 4096       // master-destination edges (expected ~800)
#define CAP_N1 24576      // nodes needing x1 (expected ~14.2K)
#define CAP_N2 4096       // nodes needing x2 (expected ~850)

// Scratch (device globals; allocation rules forbid cudaMalloc)
__device__ float g_e[(size_t)N_EDGES * 64];        // e0/e1/e2 rows at edge id (sparse)
__device__ float g_x1[(size_t)N_NODES * 128];
__device__ float g_x2[(size_t)N_NODES * 128];
__device__ float g_aggx[(size_t)N_NODES * 256];    // sum x[src] per dst (layer 1)
__device__ float g_agga[(size_t)N_NODES * 128];    // sum edge_attr per dst (layer 1)
__device__ float g_aggx2[(size_t)N_NODES * 128];   // sum relu_x1[src] per dst (layer 2)
__device__ float g_agge1[(size_t)N_NODES * 64];    // sum e1 per dst (layer 2)
__device__ float g_wpm[128 * 128];                 // w_proj @ wme1
__device__ float g_bpm[128];                       // b_proj @ wme1

__device__ int d_flag1[N_NODES];
__device__ int d_flag2[N_NODES];
__device__ int d_deg[N_NODES];
__device__ int d_list2[CAP_L2];
__device__ int d_list3[CAP_L3];
__device__ int d_nlist1[N_NODES];
__device__ int d_nlist2[CAP_N2];
__device__ int d_cnt[8];           // 0:n2 1:l2 2:l3 3:n1

struct Seg {
    const float* base;    // row-major [*, K]
    const int*   gather;  // applied to rowlist value; nullptr = value itself
    const float* W;       // [K, BN] row-major
    int K;
};

__device__ __forceinline__ unsigned long long pack2(float v) {
    unsigned long long r;
    asm("mov.b64 %0, {%1, %1};" : "=l"(r) : "f"(v));
    return r;
}
__device__ __forceinline__ void ffma2(unsigned long long& d,
                                      unsigned long long a,
                                      unsigned long long b) {
    asm("fma.rn.f32x2 %0, %1, %2, %0;" : "+l"(d) : "l"(a), "l"(b));
}
__device__ __forceinline__ float sel2(unsigned long long v, int hi) {
    float2 f = *(float2*)&v; return hi ? f.y : f.x;
}
__device__ __forceinline__ void cp16(uint32_t saddr, const float* g) {
    asm volatile("cp.async.cg.shared.global [%0], [%1], 16;" :: "r"(saddr), "l"(g));
}
__device__ __forceinline__ void cp_commit() {
    asm volatile("cp.async.commit_group;" ::: "memory");
}
__device__ __forceinline__ void cp_wait0() {
    asm volatile("cp.async.wait_group 0;" ::: "memory");
}
__device__ __forceinline__ void redv4(float* p, float4 v) {
    asm volatile("red.global.add.v4.f32 [%0], {%1,%2,%3,%4};"
                 :: "l"(p), "f"(v.x), "f"(v.y), "f"(v.z), "f"(v.w) : "memory");
}

// ---------------- frontier marking / compaction ----------------

__global__ __launch_bounds__(256) void zero_kernel()
{
    int i = blockIdx.x * 256 + threadIdx.x;
    for (int v = i; v < N_NODES; v += gridDim.x * 256) {
        d_flag1[v] = 0; d_flag2[v] = 0; d_deg[v] = 0;
    }
    if (i < 8) d_cnt[i] = 0;
}

// masters + sources of master edges need x2; collect master edges -> list3
__global__ __launch_bounds__(256) void mark2_kernel(
    const int* __restrict__ src, const int* __restrict__ dst)
{
    int e = blockIdx.x * 256 + threadIdx.x;
    if (e < N_EDGES && dst[e] % NODES_PER_GRAPH == 0) {
        d_flag2[src[e]] = 1;
        int i = atomicAdd(&d_cnt[2], 1);
        d_list3[i] = e;
    }
    if (blockIdx.x == 0 && threadIdx.x < N_GRAPHS)
        d_flag2[threadIdx.x * NODES_PER_GRAPH] = 1;
}

__global__ __launch_bounds__(256) void nodes2_kernel()
{
    int v = blockIdx.x * 256 + threadIdx.x;
    if (v < N_NODES && d_flag2[v]) {
        d_flag1[v] = 1;
        int i = atomicAdd(&d_cnt[0], 1);
        d_nlist2[i] = v;
    }
}

// edges into flag2 nodes (need e0,e1 per-edge); their srcs need x1
__global__ __launch_bounds__(256) void list2_kernel(
    const int* __restrict__ src, const int* __restrict__ dst)
{
    int e = blockIdx.x * 256 + threadIdx.x;
    if (e < N_EDGES && d_flag2[dst[e]]) {
        int i = atomicAdd(&d_cnt[1], 1);
        d_list2[i] = e;
        d_flag1[src[e]] = 1;
    }
}

__global__ __launch_bounds__(256) void nodes1_kernel()
{
    int v = blockIdx.x * 256 + threadIdx.x;
    if (v < N_NODES && d_flag1[v]) {
        int i = atomicAdd(&d_cnt[3], 1);
        d_nlist1[i] = v;
    }
}

// zero agg_x / agg_attr rows for nlist1 nodes (96 float4 per node)
__global__ __launch_bounds__(256) void zero_agg1_kernel()
{
    int n = d_cnt[3];
    int total = n * 96;
    float4 z = {0.f, 0.f, 0.f, 0.f};
    for (int i = blockIdx.x * 256 + threadIdx.x; i < total; i += gridDim.x * 256) {
        int r = i / 96, q = i % 96;
        int v = d_nlist1[r];
        if (q < 64) ((float4*)(g_aggx + (size_t)v * 256))[q] = z;
        else        ((float4*)(g_agga + (size_t)v * 128))[q - 64] = z;
    }
}

// W' = w_proj @ wme1 (128x128); bvec = b_proj @ wme1 (128)
__global__ __launch_bounds__(128) void combine_w_kernel(
    const float* __restrict__ w_proj, const float* __restrict__ b_proj,
    const float* __restrict__ wme1)
{
    int n = threadIdx.x;
    int k = blockIdx.x;
    float s = 0.f;
    if (k < 128) {
        for (int j = 0; j < 64; j++)
            s += w_proj[k * 64 + j] * wme1[j * 128 + n];
        g_wpm[k * 128 + n] = s;
    } else {
        for (int j = 0; j < 64; j++)
            s += b_proj[j] * wme1[j * 128 + n];
        g_bpm[n] = s;
    }
}

// layer-1 aggregation: for edges with flag1[dst], red-add x[src] and edge_attr[e]
__global__ __launch_bounds__(256) void agg1_kernel(
    const float* __restrict__ x, const float* __restrict__ eattr,
    const int* __restrict__ src, const int* __restrict__ dst)
{
    int warp = threadIdx.x >> 5, lane = threadIdx.x & 31;
    int e0 = (blockIdx.x * 8 + warp) * 32;
    if (e0 >= N_EDGES) return;
    int e = e0 + lane;
    int d = dst[e];
    bool hit = d_flag1[d] != 0;
    unsigned mask = __ballot_sync(0xffffffffu, hit);
    while (mask) {
        int b = __ffs(mask) - 1;
        mask &= mask - 1;
        int eh = e0 + b;
        int sh = src[eh];
        int dh = __shfl_sync(0xffffffffu, d, b);
        const float4* xr = (const float4*)(x + (size_t)sh * 256);
        redv4(g_aggx + (size_t)dh * 256 + lane * 4, xr[lane]);
        redv4(g_aggx + (size_t)dh * 256 + 128 + lane * 4, xr[lane + 32]);
        const float4* ar = (const float4*)(eattr + (size_t)eh * 128);
        redv4(g_agga + (size_t)dh * 128 + lane * 4, ar[lane]);
        if (lane == 0) atomicAdd(&d_deg[dh], 1);
    }
}

// x1[v] = bs1 + deg[v] * bvec for nlist1 nodes
__global__ __launch_bounds__(256) void seed_x1_kernel(
    float* __restrict__ x1, const float* __restrict__ bs1)
{
    int n = d_cnt[3];
    int total = n * 32;
    for (int i = blockIdx.x * 256 + threadIdx.x; i < total; i += gridDim.x * 256) {
        int r = i >> 5, c = i & 31;
        int v = d_nlist1[r];
        float dg = (float)d_deg[v];
        float4 b = ((const float4*)bs1)[c];
        float4 pv = ((const float4*)g_bpm)[c];
        float4 o = {b.x + dg * pv.x, b.y + dg * pv.y,
                    b.z + dg * pv.z, b.w + dg * pv.w};
        ((float4*)(x1 + (size_t)v * 128))[c] = o;
    }
}

// relu x1 rows in nlist1
__global__ __launch_bounds__(256) void relu_rows_kernel(float* __restrict__ x1)
{
    int n = d_cnt[3];
    int total = n * 32;
    for (int i = blockIdx.x * 256 + threadIdx.x; i < total; i += gridDim.x * 256) {
        int r = i >> 5, c = i & 31;
        float4* p = (float4*)(x1 + (size_t)d_nlist1[r] * 128) + c;
        float4 v = *p;
        v.x = fmaxf(v.x, 0.f); v.y = fmaxf(v.y, 0.f);
        v.z = fmaxf(v.z, 0.f); v.w = fmaxf(v.w, 0.f);
        *p = v;
    }
}

// zero aggx2/agge1 and seed x2 = bs2 for nlist2 nodes (80 float4 per node)
__global__ __launch_bounds__(256) void seed2_kernel(
    float* __restrict__ x2, const float* __restrict__ bs2)
{
    int n = d_cnt[0];
    int total = n * 80;
    float4 z = {0.f, 0.f, 0.f, 0.f};
    for (int i = blockIdx.x * 256 + threadIdx.x; i < total; i += gridDim.x * 256) {
        int r = i / 80, q = i % 80;
        int v = d_nlist2[r];
        if (q < 32)      ((float4*)(g_aggx2 + (size_t)v * 128))[q] = z;
        else if (q < 48) ((float4*)(g_agge1 + (size_t)v * 64))[q - 32] = z;
        else ((float4*)(x2 + (size_t)v * 128))[q - 48] = ((const float4*)bs2)[q - 48];
    }
}

// layer-2 aggregation over list2: red-add relu_x1[src] and e1[e] into dst
__global__ __launch_bounds__(256) void agg2_kernel(
    const float* __restrict__ x1, const float* __restrict__ e1,
    const int* __restrict__ src, const int* __restrict__ dst)
{
    int cnt = d_cnt[1];
    int lane = threadIdx.x & 31;
    for (int i = blockIdx.x * 8 + (threadIdx.x >> 5); i < cnt; i += gridDim.x * 8) {
        int e = d_list2[i];
        int sh = src[e];
        int dh = dst[e];
        float4 v = ((const float4*)(x1 + (size_t)sh * 128))[lane];
        redv4(g_aggx2 + (size_t)dh * 128 + lane * 4, v);
        if (lane < 16) {
            float4 u = ((const float4*)(e1 + (size_t)e * 64))[lane];
            redv4(g_agge1 + (size_t)dh * 64 + lane * 4, u);
        }
    }
}

// ---------------- pipelined gather-GEMM (f32x2 FMA, 8x8 thread tile) ----------------
// OUT=1: plain store (+bias,+relu) at scat row; OUT=2: red.global.add at scat row.
template<int BM, int BN, int BK, int NSEG, int OUT>
__global__ __launch_bounds__(256, 2) void gemm_kernel(
    Seg s0, Seg s1, Seg s2,
    const float* __restrict__ bias, int relu_out,
    float* __restrict__ out,
    const int* __restrict__ rowlist,
    const int* __restrict__ scat_map,
    const int* __restrict__ Mptr)
{
    constexpr int ASTR  = BM + 4;
    constexpr int WCOL  = BN / 64;
    constexpr int WPASS = (BK * BN) / 1024;

    const int M    = *Mptr;
    const int row0 = blockIdx.x * BM;
    if (row0 >= M) return;

    extern __shared__ float smem[];
    float* As   = smem;
    float* Wsm  = smem + 2 * BK * ASTR;
    int*   ridx = (int*)(Wsm + 2 * BK * BN);
    int*   sidx = ridx + NSEG * BM;

    Seg segs[3] = {s0, s1, s2};

    const int tid  = threadIdx.x;
    const int warp = tid >> 5;
    const int lane = tid & 31;

    const int wc = warp % WCOL;
    const int wr = warp / WCOL;
    const int ty = wr * 4 + (lane >> 3);
    const int tx = wc * 8 + (lane & 7);

    for (int i = tid; i < BM; i += 256) {
        int r = row0 + i;
        int rid = rowlist[(r < M) ? r : row0];
        #pragma unroll
        for (int s = 0; s < NSEG; s++) {
            const int* g = segs[s].gather;
            ridx[s * BM + i] = g ? g[rid] : rid;
        }
        sidx[i] = scat_map ? scat_map[rid] : rid;
    }
    __syncthreads();

    const int T0 = segs[0].K / BK;
    const int T1 = T0 + ((NSEG > 1) ? segs[1].K / BK : 0);
    const int T  = T1 + ((NSEG > 2) ? segs[2].K / BK : 0);

    const int ar_row  = (BM == 256) ? tid : (tid & (BM - 1));
    const int ar_half = (BM == 256) ? 0 : (tid >> 7);

    const float* abase[3];
    #pragma unroll
    for (int s = 0; s < NSEG; s++)
        abase[s] = segs[s].base + (size_t)ridx[s * BM + ar_row] * segs[s].K
                   + ar_half * 16;

    float4 af[4];

    auto map_tile = [&](int t, int& s, int& k0) {
        if (NSEG > 2 && t >= T1)      { s = 2; k0 = (t - T1) * BK; }
        else if (NSEG > 1 && t >= T0) { s = 1; k0 = (t - T0) * BK; }
        else                          { s = 0; k0 = t * BK; }
    };
    auto issueA = [&](int t) {
        int s, k0; map_tile(t, s, k0);
        const float* p = abase[s] + k0;
        #pragma unroll
        for (int q = 0; q < 4; q++) af[q] = *(const float4*)(p + q * 4);
    };
    auto storeA = [&](int buf) {
        float* dst = As + buf * (BK * ASTR);
        #pragma unroll
        for (int q = 0; q < 4; q++) {
            int kk = ar_half * 16 + q * 4;
            dst[(kk + 0) * ASTR + ar_row] = af[q].x;
            dst[(kk + 1) * ASTR + ar_row] = af[q].y;
            dst[(kk + 2) * ASTR + ar_row] = af[q].z;
            dst[(kk + 3) * ASTR + ar_row] = af[q].w;
        }
    };
    auto issueW = [&](int t, int buf) {
        int s, k0; map_tile(t, s, k0);
        const float* wp = segs[s].W + (size_t)k0 * BN;
        uint32_t sa = (uint32_t)__cvta_generic_to_shared(Wsm + buf * (BK * BN));
        #pragma unroll
        for (int ps = 0; ps < WPASS; ps++) {
            int i = tid * 4 + ps * 1024;
            cp16(sa + i * 4, wp + i);
        }
    };

    unsigned long long acc2[4][8];
    #pragma unroll
    for (int p = 0; p < 4; p++)
        #pragma unroll
        for (int j = 0; j < 8; j++) acc2[p][j] = 0ull;

    issueA(0); storeA(0); issueW(0, 0); cp_commit();
    if (T > 1) issueA(1);
    cp_wait0();
    __syncthreads();

    for (int t = 0; t < T; t++) {
        int buf = t & 1;
        if (t + 1 < T) { issueW(t + 1, buf ^ 1); cp_commit(); storeA(buf ^ 1); }
        if (t + 2 < T) issueA(t + 2);

        const float* as = As  + buf * (BK * ASTR);
        const float* ws = Wsm + buf * (BK * BN);
        #pragma unroll
        for (int k = 0; k < BK; k++) {
            ulonglong2 alo = *(const ulonglong2*)(as + k * ASTR + ty * 4);
            ulonglong2 ahi = *(const ulonglong2*)(as + k * ASTR + BM / 2 + ty * 4);
            float4 wlo = *(const float4*)(ws + k * BN + tx * 4);
            float4 whi = *(const float4*)(ws + k * BN + BN / 2 + tx * 4);
            unsigned long long ar[4] = {alo.x, alo.y, ahi.x, ahi.y};
            unsigned long long bd[8] = {
                pack2(wlo.x), pack2(wlo.y), pack2(wlo.z), pack2(wlo.w),
                pack2(whi.x), pack2(whi.y), pack2(whi.z), pack2(whi.w)};
            #pragma unroll
            for (int p = 0; p < 4; p++)
                #pragma unroll
                for (int j = 0; j < 8; j++)
                    ffma2(acc2[p][j], ar[p], bd[j]);
        }
        cp_wait0();
        __syncthreads();
    }

    float bv[8];
    if (OUT == 1) {
        #pragma unroll
        for (int j = 0; j < 4; j++) {
            bv[j]     = bias ? bias[tx * 4 + j] : 0.f;
            bv[4 + j] = bias ? bias[BN / 2 + tx * 4 + j] : 0.f;
        }
    }
    #pragma unroll
    for (int h = 0; h < 8; h++) {
        int hh = h & 3;
        int p  = ((h >> 2) << 1) | (hh >> 1);
        int c  = hh & 1;
        int rl = (h < 4) ? (ty * 4 + hh) : (BM / 2 + ty * 4 + hh);
        if (row0 + rl < M) {
            float* op = out + (size_t)sidx[rl] * BN;
            if (OUT == 2) {
                float v0 = sel2(acc2[p][0], c), v1 = sel2(acc2[p][1], c);
                float v2 = sel2(acc2[p][2], c), v3 = sel2(acc2[p][3], c);
                asm volatile("red.global.add.v4.f32 [%0], {%1,%2,%3,%4};"
                             :: "l"(op + tx * 4), "f"(v0), "f"(v1), "f"(v2), "f"(v3)
                             : "memory");
                float u0 = sel2(acc2[p][4], c), u1 = sel2(acc2[p][5], c);
                float u2 = sel2(acc2[p][6], c), u3 = sel2(acc2[p][7], c);
                asm volatile("red.global.add.v4.f32 [%0], {%1,%2,%3,%4};"
                             :: "l"(op + BN / 2 + tx * 4), "f"(u0), "f"(u1), "f"(u2), "f"(u3)
                             : "memory");
            } else {
                float4 o0, o1;
                o0.x = sel2(acc2[p][0], c) + bv[0];
                o0.y = sel2(acc2[p][1], c) + bv[1];
                o0.z = sel2(acc2[p][2], c) + bv[2];
                o0.w = sel2(acc2[p][3], c) + bv[3];
                o1.x = sel2(acc2[p][4], c) + bv[4];
                o1.y = sel2(acc2[p][5], c) + bv[5];
                o1.z = sel2(acc2[p][6], c) + bv[6];
                o1.w = sel2(acc2[p][7], c) + bv[7];
                if (relu_out) {
                    o0.x = fmaxf(o0.x, 0.f); o0.y = fmaxf(o0.y, 0.f);
                    o0.z = fmaxf(o0.z, 0.f); o0.w = fmaxf(o0.w, 0.f);
                    o1.x = fmaxf(o1.x, 0.f); o1.y = fmaxf(o1.y, 0.f);
                    o1.z = fmaxf(o1.z, 0.f); o1.w = fmaxf(o1.w, 0.f);
                }
                *(float4*)(op + tx * 4) = o0;
                *(float4*)(op + BN / 2 + tx * 4) = o1;
            }
        }
    }
}

// ---------------- layer-3 master kernels ----------------

__global__ __launch_bounds__(256) void master_node_kernel(
    const float* __restrict__ x2, const float* __restrict__ ws3,
    const float* __restrict__ bs3, float* __restrict__ out)
{
    int g = blockIdx.x;
    int c = threadIdx.x;
    const float* xr = x2 + (size_t)g * NODES_PER_GRAPH * 128;
    float acc = bs3[c];
    #pragma unroll 8
    for (int k = 0; k < 128; k++)
        acc += fmaxf(xr[k], 0.f) * ws3[(size_t)k * 256 + c];
    out[(size_t)g * 256 + c] = acc;
}

// out[g] += relu_x2[src]@wmx3 + e2@wme3 over list3 edges (warp per edge)
__global__ __launch_bounds__(256) void master_edge3_kernel(
    const float* __restrict__ x2, const float* __restrict__ e2,
    const int* __restrict__ src, const int* __restrict__ dst,
    const float* __restrict__ wmx3, const float* __restrict__ wme3,
    float* __restrict__ out)
{
    int cnt = d_cnt[2];
    int lane = threadIdx.x & 31;
    for (int i = blockIdx.x * 8 + (threadIdx.x >> 5); i < cnt; i += gridDim.x * 8) {
        int e = d_list3[i];
        int sh = src[e];
        int g  = dst[e] / NODES_PER_GRAPH;
        float acc[8];
        #pragma unroll
        for (int j = 0; j < 8; j++) acc[j] = 0.f;
        const float* xr = x2 + (size_t)sh * 128;
        for (int k = 0; k < 128; k++) {
            float a = fmaxf(xr[k], 0.f);
            const float* wr = wmx3 + (size_t)k * 256;
            #pragma unroll
            for (int j = 0; j < 8; j++) acc[j] += a * wr[lane + j * 32];
        }
        const float* er = e2 + (size_t)e * 64;
        for (int k = 0; k < 64; k++) {
            float a = er[k];
            const float* wr = wme3 + (size_t)k * 256;
            #pragma unroll
            for (int j = 0; j < 8; j++) acc[j] += a * wr[lane + j * 32];
        }
        float* op = out + (size_t)g * 256;
        #pragma unroll
        for (int j = 0; j < 8; j++) atomicAdd(op + lane + j * 32, acc[j]);
    }
}

template<int BM, int BN, int BK, int NSEG>
static int smem_bytes() {
    constexpr int ASTR = BM + 4;
    return (2 * BK * ASTR + 2 * BK * BN) * 4 + NSEG * BM * 4 + BM * 4;
}

extern "C" void kernel_launch(void* const* d_in, const int* in_sizes, int n_in,
                              void* d_out, int out_size)
{
    const float* x         = (const float*)d_in[0];
    const int*   edge_idx  = (const int*)d_in[1];
    const float* edge_attr = (const float*)d_in[2];
    const float* w_proj    = (const float*)d_in[4];
    const float* b_proj    = (const float*)d_in[5];
    const float* P[30];
    for (int i = 0; i < 30 && i < n_in; i++) P[i] = (const float*)d_in[i];

    const int* src = edge_idx;
    const int* dst = edge_idx + N_EDGES;
    float* out = (float*)d_out;

    void* p;
    cudaGetSymbolAddress(&p, g_e);      float* e_p    = (float*)p;
    cudaGetSymbolAddress(&p, g_x1);     float* x1_p   = (float*)p;
    cudaGetSymbolAddress(&p, g_x2);     float* x2_p   = (float*)p;
    cudaGetSymbolAddress(&p, g_aggx);   float* aggx_p = (float*)p;
    cudaGetSymbolAddress(&p, g_agga);   float* agga_p = (float*)p;
    cudaGetSymbolAddress(&p, g_aggx2);  float* aggx2_p = (float*)p;
    cudaGetSymbolAddress(&p, g_agge1);  float* agge1_p = (float*)p;
    cudaGetSymbolAddress(&p, g_wpm);    float* wpm_p  = (float*)p;
    cudaGetSymbolAddress(&p, d_list2);  const int* l2 = (const int*)p;
    cudaGetSymbolAddress(&p, d_list3);  const int* l3 = (const int*)p;
    cudaGetSymbolAddress(&p, d_nlist1); const int* n1 = (const int*)p;
    cudaGetSymbolAddress(&p, d_nlist2); const int* n2 = (const int*)p;
    cudaGetSymbolAddress(&p, d_cnt);    const int* cnt = (const int*)p;
    const int* c_n2 = cnt + 0;
    const int* c_l2 = cnt + 1;
    const int* c_n1 = cnt + 3;

    static bool attr_done = false;
    if (!attr_done) {
        cudaFuncSetAttribute(gemm_kernel<256, 64, 16, 1, 1>,
            cudaFuncAttributeMaxDynamicSharedMemorySize, smem_bytes<256, 64, 16, 1>());
        cudaFuncSetAttribute(gemm_kernel<256, 64, 16, 3, 1>,
            cudaFuncAttributeMaxDynamicSharedMemorySize, smem_bytes<256, 64, 16, 3>());
        cudaFuncSetAttribute(gemm_kernel<128, 128, 32, 3, 2>,
            cudaFuncAttributeMaxDynamicSharedMemorySize, smem_bytes<128, 128, 32, 3>());
        attr_done = true;
    }

    Seg z = {nullptr, nullptr, nullptr, 0};
    const int EGRID = N_EDGES / 256;              // 3125
    const int NGRID = (N_NODES + 255) / 256;      // 196

    // ---- frontier marking ----
    zero_kernel<<<NGRID, 256>>>();
    mark2_kernel<<<EGRID, 256>>>(src, dst);
    nodes2_kernel<<<NGRID, 256>>>();
    list2_kernel<<<EGRID, 256>>>(src, dst);
    nodes1_kernel<<<NGRID, 256>>>();
    zero_agg1_kernel<<<1024, 256>>>();
    combine_w_kernel<<<129, 128>>>(w_proj, b_proj, P[9]);   // P[9] = wme1

    // ---- layer 1 ----
    agg1_kernel<<<EGRID, 256>>>(x, edge_attr, src, dst);
    seed_x1_kernel<<<512, 256>>>(x1_p, P[7]);               // x1 = bs1 + deg*bvec
    // x1 += x@ws1 + aggx@wmx1 + agga@(w_proj@wme1)
    {
        Seg a = {x,      nullptr, P[6],  256};
        Seg b = {aggx_p, nullptr, P[8],  256};
        Seg c = {agga_p, nullptr, wpm_p, 128};
        gemm_kernel<128, 128, 32, 3, 2><<<CAP_N1 / 128, 256, smem_bytes<128, 128, 32, 3>()>>>(
            a, b, c, nullptr, 0, x1_p, n1, nullptr, c_n1);
    }
    relu_rows_kernel<<<512, 256>>>(x1_p);
    // e0 = edge_attr @ w_proj + b_proj, list2 edges only
    {
        Seg a = {edge_attr, nullptr, w_proj, 128};
        gemm_kernel<256, 64, 16, 1, 1><<<CAP_L2 / 256, 256, smem_bytes<256, 64, 16, 1>()>>>(
            a, z, z, b_proj, 0, e_p, l2, nullptr, c_l2);
    }
    // e1 = relu(x[src]@wes1 + x[dst]@wed1 + e0@wee1 + be1), list2 (in place)
    {
        Seg a = {x,   src,     P[10], 256};
        Seg b = {x,   dst,     P[11], 256};
        Seg c = {e_p, nullptr, P[12], 64};
        gemm_kernel<256, 64, 16, 3, 1><<<CAP_L2 / 256, 256, smem_bytes<256, 64, 16, 3>()>>>(
            a, b, c, P[13], 1, e_p, l2, nullptr, c_l2);
    }

    // ---- layer 2 ----
    seed2_kernel<<<256, 256>>>(x2_p, P[15]);                // x2 = bs2; zero agg2 bufs
    agg2_kernel<<<512, 256>>>(x1_p, e_p, src, dst);
    // x2 += relu_x1@ws2 + aggx2@wmx2 + agge1@wme2
    {
        Seg a = {x1_p,    nullptr, P[14], 128};
        Seg b = {aggx2_p, nullptr, P[16], 128};
        Seg c = {agge1_p, nullptr, P[17], 64};
        gemm_kernel<128, 128, 32, 3, 2><<<CAP_N2 / 128, 256, smem_bytes<128, 128, 32, 3>()>>>(
            a, b, c, nullptr, 0, x2_p, n2, nullptr, c_n2);
    }
    // e2 = relu(relu_x1[src]@wes2 + relu_x1[dst]@wed2 + e1@wee2 + be2), list3 (in place)
    {
        Seg a = {x1_p, src,     P[18], 128};
        Seg b = {x1_p, dst,     P[19], 128};
        Seg c = {e_p,  nullptr, P[20], 64};
        gemm_kernel<256, 64, 16, 3, 1><<<CAP_L3 / 256, 256, smem_bytes<256, 64, 16, 3>()>>>(
            a, b, c, P[21], 1, e_p, l3, nullptr, cnt + 2);
    }

    // ---- layer 3 ----
    master_node_kernel<<<N_GRAPHS, 256>>>(x2_p, P[22], P[23], out);
    master_edge3_kernel<<<128, 256>>>(x2_p, e_p, src, dst, P[24], P[25], out);
}

// round 9
// speedup vs baseline: 12.5669x; 1.0326x over previous
#include <cuda_runtime.h>
#include <cstddef>
#include <cstdint>

#define N_NODES 50000
#define N_EDGES 800000
#define N_GRAPHS 50
#define NODES_PER_GRAPH 1000

#define CAP_L1 327680     // edges into flag1 nodes (expected ~227K)
#define CAP_L2 32768      // edges into flag2 nodes (expected ~13.4K)
#define CAP_L3 4096       // master-destination edges (expected ~800)
#define CAP_N1 24576      // nodes needing x1 (expected ~14.2K)
#define CAP_N2 4096       // nodes needing x2 (expected ~850)

#define POS_GATHER ((const int*)(size_t)1)   // sentinel: use list position as row

// Scratch (device globals; allocation rules forbid cudaMalloc)
__device__ float g_x1[(size_t)N_NODES * 128];
__device__ float g_x2[(size_t)N_NODES * 128];
__device__ float g_aggx[(size_t)N_NODES * 256];    // sum x[src] per dst (layer 1)
__device__ float g_agga[(size_t)N_NODES * 128];    // sum edge_attr per dst (layer 1)
__device__ float g_aggx2[(size_t)N_NODES * 128];   // sum relu_x1[src] per dst (layer 2)
__device__ float g_agge1[(size_t)N_NODES * 64];    // sum e1 per dst (layer 2)
__device__ float g_ec[(size_t)CAP_L2 * 64];        // e0 rows, list2-position indexed
__device__ float g_e1c[(size_t)CAP_L2 * 64];       // e1 rows, list2-position indexed
__device__ float g_e2c[(size_t)CAP_L3 * 64];       // e2 rows, list3-position indexed
__device__ float g_wpm[128 * 128];                 // w_proj @ wme1
__device__ float g_bpm[128];                       // b_proj @ wme1

__device__ int d_flag1[N_NODES];
__device__ int d_flag2[N_NODES];
__device__ int d_deg[N_NODES];
__device__ int d_list1[CAP_L1];
__device__ int d_list2[CAP_L2];
__device__ int d_list3[CAP_L3];
__device__ int d_pos2[N_EDGES];    // edge id -> list2 position (valid for list2 edges)
__device__ int d_nlist1[N_NODES];
__device__ int d_nlist2[CAP_N2];
__device__ int d_cnt[8];           // 0:n2 1:l2 2:l3 3:n1 4:l1

struct Seg {
    const float* base;    // row-major [*, K]
    const int*   gather;  // applied to rowlist value; nullptr = value; POS_GATHER = position
    const float* W;       // [K, BN] row-major
    int K;
};

__device__ __forceinline__ unsigned long long pack2(float v) {
    unsigned long long r;
    asm("mov.b64 %0, {%1, %1};" : "=l"(r) : "f"(v));
    return r;
}
__device__ __forceinline__ void ffma2(unsigned long long& d,
                                      unsigned long long a,
                                      unsigned long long b) {
    asm("fma.rn.f32x2 %0, %1, %2, %0;" : "+l"(d) : "l"(a), "l"(b));
}
__device__ __forceinline__ float sel2(unsigned long long v, int hi) {
    float2 f = *(float2*)&v; return hi ? f.y : f.x;
}
__device__ __forceinline__ void cp16(uint32_t saddr, const float* g) {
    asm volatile("cp.async.cg.shared.global [%0], [%1], 16;" :: "r"(saddr), "l"(g));
}
__device__ __forceinline__ void cp_commit() {
    asm volatile("cp.async.commit_group;" ::: "memory");
}
__device__ __forceinline__ void cp_wait0() {
    asm volatile("cp.async.wait_group 0;" ::: "memory");
}
__device__ __forceinline__ void redv4(float* p, float4 v) {
    asm volatile("red.global.add.v4.f32 [%0], {%1,%2,%3,%4};"
                 :: "l"(p), "f"(v.x), "f"(v.y), "f"(v.z), "f"(v.w) : "memory");
}

// ---------------- frontier marking / compaction ----------------

__global__ __launch_bounds__(256) void zero_kernel()
{
    int i = blockIdx.x * 256 + threadIdx.x;
    for (int v = i; v < N_NODES; v += gridDim.x * 256) {
        d_flag1[v] = 0; d_flag2[v] = 0; d_deg[v] = 0;
    }
    if (i < 8) d_cnt[i] = 0;
}

// vectorized: masters + sources of master edges; master edges -> list3
__global__ __launch_bounds__(256) void mark2_scan(
    const int* __restrict__ src, const int* __restrict__ dst)
{
    int n4 = N_EDGES / 4;
    for (int i = blockIdx.x * 256 + threadIdx.x; i < n4; i += gridDim.x * 256) {
        int4 d = ((const int4*)dst)[i];
        int e = i * 4;
        if (d.x % NODES_PER_GRAPH == 0) { d_flag2[src[e+0]] = 1; d_list3[atomicAdd(&d_cnt[2],1)] = e+0; }
        if (d.y % NODES_PER_GRAPH == 0) { d_flag2[src[e+1]] = 1; d_list3[atomicAdd(&d_cnt[2],1)] = e+1; }
        if (d.z % NODES_PER_GRAPH == 0) { d_flag2[src[e+2]] = 1; d_list3[atomicAdd(&d_cnt[2],1)] = e+2; }
        if (d.w % NODES_PER_GRAPH == 0) { d_flag2[src[e+3]] = 1; d_list3[atomicAdd(&d_cnt[2],1)] = e+3; }
    }
    if (blockIdx.x == 0 && threadIdx.x < N_GRAPHS)
        d_flag2[threadIdx.x * NODES_PER_GRAPH] = 1;
}

__global__ __launch_bounds__(256) void nodes2_kernel()
{
    int v = blockIdx.x * 256 + threadIdx.x;
    if (v < N_NODES && d_flag2[v]) {
        d_flag1[v] = 1;
        int i = atomicAdd(&d_cnt[0], 1);
        d_nlist2[i] = v;
    }
}

// vectorized: edges into flag2 nodes -> list2 (+pos map); their srcs need x1
__global__ __launch_bounds__(256) void list2_scan(
    const int* __restrict__ src, const int* __restrict__ dst)
{
    int n4 = N_EDGES / 4;
    for (int i = blockIdx.x * 256 + threadIdx.x; i < n4; i += gridDim.x * 256) {
        int4 d = ((const int4*)dst)[i];
        int e = i * 4;
        #pragma unroll
        for (int q = 0; q < 4; q++) {
            int dd = (q == 0) ? d.x : (q == 1) ? d.y : (q == 2) ? d.z : d.w;
            int ee = e + q;
            if (d_flag2[dd]) {
                int j = atomicAdd(&d_cnt[1], 1);
                d_list2[j] = ee;
                d_pos2[ee] = j;
                d_flag1[src[ee]] = 1;
            }
        }
    }
}

// vectorized: edges into flag1 nodes -> list1
__global__ __launch_bounds__(256) void list1_scan(const int* __restrict__ dst)
{
    int n4 = N_EDGES / 4;
    for (int i = blockIdx.x * 256 + threadIdx.x; i < n4; i += gridDim.x * 256) {
        int4 d = ((const int4*)dst)[i];
        int e = i * 4;
        if (d_flag1[d.x]) d_list1[atomicAdd(&d_cnt[4],1)] = e+0;
        if (d_flag1[d.y]) d_list1[atomicAdd(&d_cnt[4],1)] = e+1;
        if (d_flag1[d.z]) d_list1[atomicAdd(&d_cnt[4],1)] = e+2;
        if (d_flag1[d.w]) d_list1[atomicAdd(&d_cnt[4],1)] = e+3;
    }
}

__global__ __launch_bounds__(256) void nodes1_kernel()
{
    int v = blockIdx.x * 256 + threadIdx.x;
    if (v < N_NODES && d_flag1[v]) {
        int i = atomicAdd(&d_cnt[3], 1);
        d_nlist1[i] = v;
    }
}

// zero agg_x / agg_attr rows for nlist1 nodes (96 float4 per node)
__global__ __launch_bounds__(256) void zero_agg1_kernel()
{
    int n = d_cnt[3];
    int total = n * 96;
    float4 z = {0.f, 0.f, 0.f, 0.f};
    for (int i = blockIdx.x * 256 + threadIdx.x; i < total; i += gridDim.x * 256) {
        int r = i / 96, q = i % 96;
        int v = d_nlist1[r];
        if (q < 64) ((float4*)(g_aggx + (size_t)v * 256))[q] = z;
        else        ((float4*)(g_agga + (size_t)v * 128))[q - 64] = z;
    }
}

// W' = w_proj @ wme1 (128x128); bvec = b_proj @ wme1 (128)
__global__ __launch_bounds__(128) void combine_w_kernel(
    const float* __restrict__ w_proj, const float* __restrict__ b_proj,
    const float* __restrict__ wme1)
{
    int n = threadIdx.x;
    int k = blockIdx.x;
    float s = 0.f;
    if (k < 128) {
        for (int j = 0; j < 64; j++)
            s += w_proj[k * 64 + j] * wme1[j * 128 + n];
        g_wpm[k * 128 + n] = s;
    } else {
        for (int j = 0; j < 64; j++)
            s += b_proj[j] * wme1[j * 128 + n];
        g_bpm[n] = s;
    }
}

// layer-1 aggregation over list1: red-add x[src] (256f), edge_attr (128f), deg
__global__ __launch_bounds__(256) void agg1_kernel(
    const float* __restrict__ x, const float* __restrict__ eattr,
    const int* __restrict__ src, const int* __restrict__ dst)
{
    int cnt = d_cnt[4];
    int lane = threadIdx.x & 31;
    for (int i = blockIdx.x * 8 + (threadIdx.x >> 5); i < cnt; i += gridDim.x * 8) {
        int e  = d_list1[i];
        int sh = src[e];
        int dh = dst[e];
        const float4* xr = (const float4*)(x + (size_t)sh * 256);
        redv4(g_aggx + (size_t)dh * 256 + lane * 4, xr[lane]);
        redv4(g_aggx + (size_t)dh * 256 + 128 + lane * 4, xr[lane + 32]);
        const float4* ar = (const float4*)(eattr + (size_t)e * 128);
        redv4(g_agga + (size_t)dh * 128 + lane * 4, ar[lane]);
        if (lane == 0) atomicAdd(&d_deg[dh], 1);
    }
}

// x1[v] = bs1 + deg[v] * bvec for nlist1 nodes
__global__ __launch_bounds__(256) void seed_x1_kernel(
    float* __restrict__ x1, const float* __restrict__ bs1)
{
    int n = d_cnt[3];
    int total = n * 32;
    for (int i = blockIdx.x * 256 + threadIdx.x; i < total; i += gridDim.x * 256) {
        int r = i >> 5, c = i & 31;
        int v = d_nlist1[r];
        float dg = (float)d_deg[v];
        float4 b = ((const float4*)bs1)[c];
        float4 pv = ((const float4*)g_bpm)[c];
        float4 o = {b.x + dg * pv.x, b.y + dg * pv.y,
                    b.z + dg * pv.z, b.w + dg * pv.w};
        ((float4*)(x1 + (size_t)v * 128))[c] = o;
    }
}

// relu x1 rows in nlist1
__global__ __launch_bounds__(256) void relu_rows_kernel(float* __restrict__ x1)
{
    int n = d_cnt[3];
    int total = n * 32;
    for (int i = blockIdx.x * 256 + threadIdx.x; i < total; i += gridDim.x * 256) {
        int r = i >> 5, c = i & 31;
        float4* p = (float4*)(x1 + (size_t)d_nlist1[r] * 128) + c;
        float4 v = *p;
        v.x = fmaxf(v.x, 0.f); v.y = fmaxf(v.y, 0.f);
        v.z = fmaxf(v.z, 0.f); v.w = fmaxf(v.w, 0.f);
        *p = v;
    }
}

// seed compact 64-wide rows [0,cnt) with bias
__global__ __launch_bounds__(256) void seed_rows64_kernel(
    float* __restrict__ buf, const float* __restrict__ bias, const int* __restrict__ cntp)
{
    int total = *cntp * 16;
    for (int i = blockIdx.x * 256 + threadIdx.x; i < total; i += gridDim.x * 256)
        ((float4*)buf)[i] = ((const float4*)bias)[i & 15];
}

// relu compact 64-wide rows [0,cnt)
__global__ __launch_bounds__(256) void relu_rows64_kernel(
    float* __restrict__ buf, const int* __restrict__ cntp)
{
    int total = *cntp * 16;
    for (int i = blockIdx.x * 256 + threadIdx.x; i < total; i += gridDim.x * 256) {
        float4 v = ((float4*)buf)[i];
        v.x = fmaxf(v.x, 0.f); v.y = fmaxf(v.y, 0.f);
        v.z = fmaxf(v.z, 0.f); v.w = fmaxf(v.w, 0.f);
        ((float4*)buf)[i] = v;
    }
}

// zero aggx2/agge1 and seed x2 = bs2 for nlist2 nodes
__global__ __launch_bounds__(256) void seed2_kernel(
    float* __restrict__ x2, const float* __restrict__ bs2)
{
    int n = d_cnt[0];
    int total = n * 80;
    float4 z = {0.f, 0.f, 0.f, 0.f};
    for (int i = blockIdx.x * 256 + threadIdx.x; i < total; i += gridDim.x * 256) {
        int r = i / 80, q = i % 80;
        int v = d_nlist2[r];
        if (q < 32)      ((float4*)(g_aggx2 + (size_t)v * 128))[q] = z;
        else if (q < 48) ((float4*)(g_agge1 + (size_t)v * 64))[q - 32] = z;
        else ((float4*)(x2 + (size_t)v * 128))[q - 48] = ((const float4*)bs2)[q - 48];
    }
}

// layer-2 aggregation over list2 positions: red-add relu_x1[src], e1 (compact)
__global__ __launch_bounds__(256) void agg2_kernel(
    const float* __restrict__ x1,
    const int* __restrict__ src, const int* __restrict__ dst)
{
    int cnt = d_cnt[1];
    int lane = threadIdx.x & 31;
    for (int i = blockIdx.x * 8 + (threadIdx.x >> 5); i < cnt; i += gridDim.x * 8) {
        int e  = d_list2[i];
        int sh = src[e];
        int dh = dst[e];
        float4 v = ((const float4*)(x1 + (size_t)sh * 128))[lane];
        redv4(g_aggx2 + (size_t)dh * 128 + lane * 4, v);
        if (lane < 16) {
            float4 u = ((const float4*)(g_e1c + (size_t)i * 64))[lane];
            redv4(g_agge1 + (size_t)dh * 64 + lane * 4, u);
        }
    }
}

// ---------------- pipelined gather-GEMM (f32x2 FMA, 8x8 thread tile) ----------------
// OUT=1: store (+bias,+relu) at scat row; OUT=2: red.global.add at scat row.
// gridDim.y = split-K factor (tile-range partition; only valid with OUT=2 or y==1).
template<int BM, int BN, int BK, int NSEG, int OUT>
__global__ __launch_bounds__(256, 2) void gemm_kernel(
    Seg s0, Seg s1, Seg s2,
    const float* __restrict__ bias, int relu_out,
    float* __restrict__ out,
    const int* __restrict__ rowlist,
    const int* __restrict__ scat_map,
    const int* __restrict__ Mptr)
{
    constexpr int ASTR  = BM + 4;
    constexpr int WCOL  = BN / 64;
    constexpr int WPASS = (BK * BN) / 1024;

    const int M    = *Mptr;
    const int row0 = blockIdx.x * BM;
    if (row0 >= M) return;

    extern __shared__ float smem[];
    float* As   = smem;
    float* Wsm  = smem + 2 * BK * ASTR;
    int*   ridx = (int*)(Wsm + 2 * BK * BN);
    int*   sidx = ridx + NSEG * BM;

    Seg segs[3] = {s0, s1, s2};

    const int tid  = threadIdx.x;
    const int warp = tid >> 5;
    const int lane = tid & 31;

    const int wc = warp % WCOL;
    const int wr = warp / WCOL;
    const int ty = wr * 4 + (lane >> 3);
    const int tx = wc * 8 + (lane & 7);

    for (int i = tid; i < BM; i += 256) {
        int r = row0 + i;
        int rc = (r < M) ? r : row0;
        int rid = rowlist[rc];
        #pragma unroll
        for (int s = 0; s < NSEG; s++) {
            const int* g = segs[s].gather;
            ridx[s * BM + i] = (g == POS_GATHER) ? rc : (g ? g[rid] : rid);
        }
        sidx[i] = (scat_map == POS_GATHER) ? rc : (scat_map ? scat_map[rid] : rid);
    }
    __syncthreads();

    const int T0 = segs[0].K / BK;
    const int T1 = T0 + ((NSEG > 1) ? segs[1].K / BK : 0);
    const int T  = T1 + ((NSEG > 2) ? segs[2].K / BK : 0);
    const int ts = T * blockIdx.y / gridDim.y;
    const int te = T * (blockIdx.y + 1) / gridDim.y;

    const int ar_row  = (BM == 256) ? tid : (tid & (BM - 1));
    const int ar_half = (BM == 256) ? 0 : (tid >> 7);

    const float* abase[3];
    #pragma unroll
    for (int s = 0; s < NSEG; s++)
        abase[s] = segs[s].base + (size_t)ridx[s * BM + ar_row] * segs[s].K
                   + ar_half * 16;

    float4 af[4];

    auto map_tile = [&](int t, int& s, int& k0) {
        if (NSEG > 2 && t >= T1)      { s = 2; k0 = (t - T1) * BK; }
        else if (NSEG > 1 && t >= T0) { s = 1; k0 = (t - T0) * BK; }
        else                          { s = 0; k0 = t * BK; }
    };
    auto issueA = [&](int t) {
        int s, k0; map_tile(t, s, k0);
        const float* p = abase[s] + k0;
        #pragma unroll
        for (int q = 0; q < 4; q++) af[q] = *(const float4*)(p + q * 4);
    };
    auto storeA = [&](int buf) {
        float* dst = As + buf * (BK * ASTR);
        #pragma unroll
        for (int q = 0; q < 4; q++) {
            int kk = ar_half * 16 + q * 4;
            dst[(kk + 0) * ASTR + ar_row] = af[q].x;
            dst[(kk + 1) * ASTR + ar_row] = af[q].y;
            dst[(kk + 2) * ASTR + ar_row] = af[q].z;
            dst[(kk + 3) * ASTR + ar_row] = af[q].w;
        }
    };
    auto issueW = [&](int t, int buf) {
        int s, k0; map_tile(t, s, k0);
        const float* wp = segs[s].W + (size_t)k0 * BN;
        uint32_t sa = (uint32_t)__cvta_generic_to_shared(Wsm + buf * (BK * BN));
        #pragma unroll
        for (int ps = 0; ps < WPASS; ps++) {
            int i = tid * 4 + ps * 1024;
            cp16(sa + i * 4, wp + i);
        }
    };

    unsigned long long acc2[4][8];
    #pragma unroll
    for (int p = 0; p < 4; p++)
        #pragma unroll
        for (int j = 0; j < 8; j++) acc2[p][j] = 0ull;

    issueA(ts); storeA(0); issueW(ts, 0); cp_commit();
    if (ts + 1 < te) issueA(ts + 1);
    cp_wait0();
    __syncthreads();

    for (int t = ts; t < te; t++) {
        int buf = (t - ts) & 1;
        if (t + 1 < te) { issueW(t + 1, buf ^ 1); cp_commit(); storeA(buf ^ 1); }
        if (t + 2 < te) issueA(t + 2);

        const float* as = As  + buf * (BK * ASTR);
        const float* ws = Wsm + buf * (BK * BN);
        #pragma unroll
        for (int k = 0; k < BK; k++) {
            ulonglong2 alo = *(const ulonglong2*)(as + k * ASTR + ty * 4);
            ulonglong2 ahi = *(const ulonglong2*)(as + k * ASTR + BM / 2 + ty * 4);
            float4 wlo = *(const float4*)(ws + k * BN + tx * 4);
            float4 whi = *(const float4*)(ws + k * BN + BN / 2 + tx * 4);
            unsigned long long ar[4] = {alo.x, alo.y, ahi.x, ahi.y};
            unsigned long long bd[8] = {
                pack2(wlo.x), pack2(wlo.y), pack2(wlo.z), pack2(wlo.w),
                pack2(whi.x), pack2(whi.y), pack2(whi.z), pack2(whi.w)};
            #pragma unroll
            for (int p = 0; p < 4; p++)
                #pragma unroll
                for (int j = 0; j < 8; j++)
                    ffma2(acc2[p][j], ar[p], bd[j]);
        }
        cp_wait0();
        __syncthreads();
    }

    float bv[8];
    if (OUT == 1) {
        #pragma unroll
        for (int j = 0; j < 4; j++) {
            bv[j]     = bias ? bias[tx * 4 + j] : 0.f;
            bv[4 + j] = bias ? bias[BN / 2 + tx * 4 + j] : 0.f;
        }
    }
    #pragma unroll
    for (int h = 0; h < 8; h++) {
        int hh = h & 3;
        int p  = ((h >> 2) << 1) | (hh >> 1);
        int c  = hh & 1;
        int rl = (h < 4) ? (ty * 4 + hh) : (BM / 2 + ty * 4 + hh);
        if (row0 + rl < M) {
            float* op = out + (size_t)sidx[rl] * BN;
            if (OUT == 2) {
                float v0 = sel2(acc2[p][0], c), v1 = sel2(acc2[p][1], c);
                float v2 = sel2(acc2[p][2], c), v3 = sel2(acc2[p][3], c);
                asm volatile("red.global.add.v4.f32 [%0], {%1,%2,%3,%4};"
                             :: "l"(op + tx * 4), "f"(v0), "f"(v1), "f"(v2), "f"(v3)
                             : "memory");
                float u0 = sel2(acc2[p][4], c), u1 = sel2(acc2[p][5], c);
                float u2 = sel2(acc2[p][6], c), u3 = sel2(acc2[p][7], c);
                asm volatile("red.global.add.v4.f32 [%0], {%1,%2,%3,%4};"
                             :: "l"(op + BN / 2 + tx * 4), "f"(u0), "f"(u1), "f"(u2), "f"(u3)
                             : "memory");
            } else {
                float4 o0, o1;
                o0.x = sel2(acc2[p][0], c) + bv[0];
                o0.y = sel2(acc2[p][1], c) + bv[1];
                o0.z = sel2(acc2[p][2], c) + bv[2];
                o0.w = sel2(acc2[p][3], c) + bv[3];
                o1.x = sel2(acc2[p][4], c) + bv[4];
                o1.y = sel2(acc2[p][5], c) + bv[5];
                o1.z = sel2(acc2[p][6], c) + bv[6];
                o1.w = sel2(acc2[p][7], c) + bv[7];
                if (relu_out) {
                    o0.x = fmaxf(o0.x, 0.f); o0.y = fmaxf(o0.y, 0.f);
                    o0.z = fmaxf(o0.z, 0.f); o0.w = fmaxf(o0.w, 0.f);
                    o1.x = fmaxf(o1.x, 0.f); o1.y = fmaxf(o1.y, 0.f);
                    o1.z = fmaxf(o1.z, 0.f); o1.w = fmaxf(o1.w, 0.f);
                }
                *(float4*)(op + tx * 4) = o0;
                *(float4*)(op + BN / 2 + tx * 4) = o1;
            }
        }
    }
}

// ---------------- layer-3 master kernels ----------------

__global__ __launch_bounds__(256) void master_node_kernel(
    const float* __restrict__ x2, const float* __restrict__ ws3,
    const float* __restrict__ bs3, float* __restrict__ out)
{
    int g = blockIdx.x;
    int c = threadIdx.x;
    const float* xr = x2 + (size_t)g * NODES_PER_GRAPH * 128;
    float acc = bs3[c];
    #pragma unroll 8
    for (int k = 0; k < 128; k++)
        acc += fmaxf(xr[k], 0.f) * ws3[(size_t)k * 256 + c];
    out[(size_t)g * 256 + c] = acc;
}

// out[g] += relu_x2[src]@wmx3 + e2@wme3 over list3 positions (warp per edge)
__global__ __launch_bounds__(256) void master_edge3_kernel(
    const float* __restrict__ x2,
    const int* __restrict__ src, const int* __restrict__ dst,
    const float* __restrict__ wmx3, const float* __restrict__ wme3,
    float* __restrict__ out)
{
    int cnt = d_cnt[2];
    int lane = threadIdx.x & 31;
    for (int i = blockIdx.x * 8 + (threadIdx.x >> 5); i < cnt; i += gridDim.x * 8) {
        int e  = d_list3[i];
        int sh = src[e];
        int g  = dst[e] / NODES_PER_GRAPH;
        float acc[8];
        #pragma unroll
        for (int j = 0; j < 8; j++) acc[j] = 0.f;
        const float* xr = x2 + (size_t)sh * 128;
        for (int k = 0; k < 128; k++) {
            float a = fmaxf(xr[k], 0.f);
            const float* wr = wmx3 + (size_t)k * 256;
            #pragma unroll
            for (int j = 0; j < 8; j++) acc[j] += a * wr[lane + j * 32];
        }
        const float* er = g_e2c + (size_t)i * 64;
        for (int k = 0; k < 64; k++) {
            float a = er[k];
            const float* wr = wme3 + (size_t)k * 256;
            #pragma unroll
            for (int j = 0; j < 8; j++) acc[j] += a * wr[lane + j * 32];
        }
        float* op = out + (size_t)g * 256;
        #pragma unroll
        for (int j = 0; j < 8; j++) atomicAdd(op + lane + j * 32, acc[j]);
    }
}

template<int BM, int BN, int BK, int NSEG>
static int smem_bytes() {
    constexpr int ASTR = BM + 4;
    return (2 * BK * ASTR + 2 * BK * BN) * 4 + NSEG * BM * 4 + BM * 4;
}

extern "C" void kernel_launch(void* const* d_in, const int* in_sizes, int n_in,
                              void* d_out, int out_size)
{
    const float* x         = (const float*)d_in[0];
    const int*   edge_idx  = (const int*)d_in[1];
    const float* edge_attr = (const float*)d_in[2];
    const float* w_proj    = (const float*)d_in[4];
    const float* b_proj    = (const float*)d_in[5];
    const float* P[30];
    for (int i = 0; i < 30 && i < n_in; i++) P[i] = (const float*)d_in[i];

    const int* src = edge_idx;
    const int* dst = edge_idx + N_EDGES;
    float* out = (float*)d_out;

    void* p;
    cudaGetSymbolAddress(&p, g_x1);     float* x1_p    = (float*)p;
    cudaGetSymbolAddress(&p, g_x2);     float* x2_p    = (float*)p;
    cudaGetSymbolAddress(&p, g_aggx);   float* aggx_p  = (float*)p;
    cudaGetSymbolAddress(&p, g_agga);   float* agga_p  = (float*)p;
    cudaGetSymbolAddress(&p, g_aggx2);  float* aggx2_p = (float*)p;
    cudaGetSymbolAddress(&p, g_agge1);  float* agge1_p = (float*)p;
    cudaGetSymbolAddress(&p, g_ec);     float* ec_p    = (float*)p;
    cudaGetSymbolAddress(&p, g_e1c);    float* e1c_p   = (float*)p;
    cudaGetSymbolAddress(&p, g_e2c);    float* e2c_p   = (float*)p;
    cudaGetSymbolAddress(&p, g_wpm);    float* wpm_p   = (float*)p;
    cudaGetSymbolAddress(&p, d_list2);  const int* l2  = (const int*)p;
    cudaGetSymbolAddress(&p, d_list3);  const int* l3  = (const int*)p;
    cudaGetSymbolAddress(&p, d_pos2);   const int* pos2 = (const int*)p;
    cudaGetSymbolAddress(&p, d_nlist1); const int* n1  = (const int*)p;
    cudaGetSymbolAddress(&p, d_nlist2); const int* n2  = (const int*)p;
    cudaGetSymbolAddress(&p, d_cnt);    const int* cnt = (const int*)p;
    const int* c_n2 = cnt + 0;
    const int* c_l2 = cnt + 1;
    const int* c_l3 = cnt + 2;
    const int* c_n1 = cnt + 3;

    static bool attr_done = false;
    if (!attr_done) {
        cudaFuncSetAttribute(gemm_kernel<256, 64, 16, 1, 1>,
            cudaFuncAttributeMaxDynamicSharedMemorySize, smem_bytes<256, 64, 16, 1>());
        cudaFuncSetAttribute(gemm_kernel<256, 64, 16, 3, 2>,
            cudaFuncAttributeMaxDynamicSharedMemorySize, smem_bytes<256, 64, 16, 3>());
        cudaFuncSetAttribute(gemm_kernel<128, 128, 32, 3, 2>,
            cudaFuncAttributeMaxDynamicSharedMemorySize, smem_bytes<128, 128, 32, 3>());
        attr_done = true;
    }

    Seg z = {nullptr, nullptr, nullptr, 0};
    const int NGRID = (N_NODES + 255) / 256;      // 196

    // ---- frontier marking ----
    zero_kernel<<<NGRID, 256>>>();
    mark2_scan<<<512, 256>>>(src, dst);
    nodes2_kernel<<<NGRID, 256>>>();
    list2_scan<<<512, 256>>>(src, dst);
    list1_scan<<<512, 256>>>(dst);
    nodes1_kernel<<<NGRID, 256>>>();
    zero_agg1_kernel<<<1024, 256>>>();
    combine_w_kernel<<<129, 128>>>(w_proj, b_proj, P[9]);   // P[9] = wme1

    // ---- layer 1 ----
    agg1_kernel<<<1536, 256>>>(x, edge_attr, src, dst);
    seed_x1_kernel<<<512, 256>>>(x1_p, P[7]);
    // x1 += x@ws1 + aggx@wmx1 + agga@(w_proj@wme1)   [split-K 2]
    {
        Seg a = {x,      nullptr, P[6],  256};
        Seg b = {aggx_p, nullptr, P[8],  256};
        Seg c = {agga_p, nullptr, wpm_p, 128};
        gemm_kernel<128, 128, 32, 3, 2>
            <<<dim3(CAP_N1 / 128, 2), 256, smem_bytes<128, 128, 32, 3>()>>>(
            a, b, c, nullptr, 0, x1_p, n1, nullptr, c_n1);
    }
    relu_rows_kernel<<<512, 256>>>(x1_p);
    // e0 = edge_attr @ w_proj + b_proj -> compact rows at list2 positions
    {
        Seg a = {edge_attr, nullptr, w_proj, 128};
        gemm_kernel<256, 64, 16, 1, 1>
            <<<CAP_L2 / 256, 256, smem_bytes<256, 64, 16, 1>()>>>(
            a, z, z, b_proj, 0, ec_p, l2, POS_GATHER, c_l2);
    }
    // e1 = relu(x[src]@wes1 + x[dst]@wed1 + e0@wee1 + be1)  [seed + split-K 2 + relu]
    seed_rows64_kernel<<<256, 256>>>(e1c_p, P[13], c_l2);
    {
        Seg a = {x,    src,        P[10], 256};
        Seg b = {x,    dst,        P[11], 256};
        Seg c = {ec_p, POS_GATHER, P[12], 64};
        gemm_kernel<256, 64, 16, 3, 2>
            <<<dim3(CAP_L2 / 256, 2), 256, smem_bytes<256, 64, 16, 3>()>>>(
            a, b, c, nullptr, 0, e1c_p, l2, POS_GATHER, c_l2);
    }
    relu_rows64_kernel<<<256, 256>>>(e1c_p, c_l2);

    // ---- layer 2 ----
    seed2_kernel<<<256, 256>>>(x2_p, P[15]);
    agg2_kernel<<<512, 256>>>(x1_p, src, dst);
    // x2 += relu_x1@ws2 + aggx2@wmx2 + agge1@wme2   [split-K 4]
    {
        Seg a = {x1_p,    nullptr, P[14], 128};
        Seg b = {aggx2_p, nullptr, P[16], 128};
        Seg c = {agge1_p, nullptr, P[17], 64};
        gemm_kernel<128, 128, 32, 3, 2>
            <<<dim3(CAP_N2 / 128, 4), 256, smem_bytes<128, 128, 32, 3>()>>>(
            a, b, c, nullptr, 0, x2_p, n2, nullptr, c_n2);
    }
    // e2 = relu(relu_x1[src]@wes2 + relu_x1[dst]@wed2 + e1@wee2 + be2)  [seed + split-K 4 + relu]
    seed_rows64_kernel<<<64, 256>>>(e2c_p, P[21], c_l3);
    {
        Seg a = {x1_p,  src,   P[18], 128};
        Seg b = {x1_p,  dst,   P[19], 128};
        Seg c = {e1c_p, pos2,  P[20], 64};
        gemm_kernel<256, 64, 16, 3, 2>
            <<<dim3(CAP_L3 / 256, 4), 256, smem_bytes<256, 64, 16, 3>()>>>(
            a, b, c, nullptr, 0, e2c_p, l3, POS_GATHER, c_l3);
    }
    relu_rows64_kernel<<<64, 256>>>(e2c_p, c_l3);

    // ---- layer 3 ----
    master_node_kernel<<<N_GRAPHS, 256>>>(x2_p, P[22], P[23], out);
    master_edge3_kernel<<<128, 256>>>(x2_p, src, dst, P[24], P[25], out);
}

// round 10
// speedup vs baseline: 16.8595x; 1.3416x over previous
#include <cuda_runtime.h>
#include <cstddef>
#include <cstdint>

#define N_NODES 50000
#define N_EDGES 800000
#define N_GRAPHS 50
#define NODES_PER_GRAPH 1000

#define CAP_L2 32768      // edges into flag2 nodes (expected ~13.4K)
#define CAP_L3 4096       // master-destination edges (expected ~800)
#define CAP_N1 24576      // nodes needing x1 (expected ~14.2K)
#define CAP_N2 4096       // nodes needing x2 (expected ~850)

#define POS_GATHER ((const int*)(size_t)1)   // sentinel: use list position as row

// Scratch (device globals; allocation rules forbid cudaMalloc)
__device__ float g_x1[(size_t)N_NODES * 128];
__device__ float g_x2[(size_t)N_NODES * 128];
__device__ float g_aggx[(size_t)N_NODES * 256];    // sum x[src] per dst (layer 1)
__device__ float g_agga[(size_t)N_NODES * 128];    // sum edge_attr per dst (layer 1)
__device__ float g_aggx2[(size_t)N_NODES * 128];   // sum relu_x1[src] per dst (layer 2)
__device__ float g_agge1[(size_t)N_NODES * 64];    // sum e1 per dst (layer 2)
__device__ float g_ec[(size_t)CAP_L2 * 64];        // e0 rows, list2-position indexed
__device__ float g_e1c[(size_t)CAP_L2 * 64];       // e1 rows, list2-position indexed
__device__ float g_e2c[(size_t)CAP_L3 * 64];       // e2 rows, list3-position indexed
__device__ float g_wpm[128 * 128];                 // w_proj @ wme1
__device__ float g_bpm[128];                       // b_proj @ wme1

__device__ int d_flag1[N_NODES];
__device__ int d_flag2[N_NODES];
__device__ int d_deg[N_NODES];
__device__ int d_list2[CAP_L2];
__device__ int d_list3[CAP_L3];
__device__ int d_pos2[N_EDGES];    // edge id -> list2 position (valid for list2 edges)
__device__ int d_nlist1[N_NODES];
__device__ int d_nlist2[CAP_N2];
__device__ int d_cnt[8];           // 0:n2 1:l2 2:l3 3:n1

struct Seg {
    const float* base;    // row-major [*, K]
    const int*   gather;  // applied to rowlist value; nullptr = value; POS_GATHER = position
    const float* W;       // [K, BN] row-major
    int K;
};

__device__ __forceinline__ unsigned long long pack2(float v) {
    unsigned long long r;
    asm("mov.b64 %0, {%1, %1};" : "=l"(r) : "f"(v));
    return r;
}
__device__ __forceinline__ void ffma2(unsigned long long& d,
                                      unsigned long long a,
                                      unsigned long long b) {
    asm("fma.rn.f32x2 %0, %1, %2, %0;" : "+l"(d) : "l"(a), "l"(b));
}
__device__ __forceinline__ float sel2(unsigned long long v, int hi) {
    float2 f = *(float2*)&v; return hi ? f.y : f.x;
}
__device__ __forceinline__ void cp16(uint32_t saddr, const float* g) {
    asm volatile("cp.async.cg.shared.global [%0], [%1], 16;" :: "r"(saddr), "l"(g));
}
__device__ __forceinline__ void cp_commit() {
    asm volatile("cp.async.commit_group;" ::: "memory");
}
__device__ __forceinline__ void cp_wait0() {
    asm volatile("cp.async.wait_group 0;" ::: "memory");
}
__device__ __forceinline__ void redv4(float* p, float4 v) {
    asm volatile("red.global.add.v4.f32 [%0], {%1,%2,%3,%4};"
                 :: "l"(p), "f"(v.x), "f"(v.y), "f"(v.z), "f"(v.w) : "memory");
}

// ---------------- frontier marking / compaction ----------------

__global__ __launch_bounds__(256) void zero_kernel()
{
    int n4 = N_NODES / 4;   // 12500
    int4 z = {0, 0, 0, 0};
    for (int i = blockIdx.x * 256 + threadIdx.x; i < n4; i += gridDim.x * 256) {
        ((int4*)d_flag1)[i] = z;
        ((int4*)d_flag2)[i] = z;
        ((int4*)d_deg)[i]   = z;
    }
    if (blockIdx.x == 0 && threadIdx.x < 8) d_cnt[threadIdx.x] = 0;
}

// fused: flag2/nlist2 (dedup via atomicExch) for masters + sources of master
// edges; master edges -> list3; flag1 |= flag2
__global__ __launch_bounds__(256) void mark2_scan(
    const int* __restrict__ src, const int* __restrict__ dst)
{
    int n4 = N_EDGES / 4;
    for (int i = blockIdx.x * 256 + threadIdx.x; i < n4; i += gridDim.x * 256) {
        int4 d = ((const int4*)dst)[i];
        int e = i * 4;
        #pragma unroll
        for (int q = 0; q < 4; q++) {
            int dd = (q == 0) ? d.x : (q == 1) ? d.y : (q == 2) ? d.z : d.w;
            if (dd % NODES_PER_GRAPH == 0) {
                int s = src[e + q];
                if (atomicExch(&d_flag2[s], 1) == 0) {
                    d_flag1[s] = 1;
                    d_nlist2[atomicAdd(&d_cnt[0], 1)] = s;
                }
                d_list3[atomicAdd(&d_cnt[2], 1)] = e + q;
            }
        }
    }
    if (blockIdx.x == 0 && threadIdx.x < N_GRAPHS) {
        int v = threadIdx.x * NODES_PER_GRAPH;
        if (atomicExch(&d_flag2[v], 1) == 0) {
            d_flag1[v] = 1;
            d_nlist2[atomicAdd(&d_cnt[0], 1)] = v;
        }
    }
}

// edges into flag2 nodes -> list2 (+pos map); their srcs need x1
__global__ __launch_bounds__(256) void list2_scan(
    const int* __restrict__ src, const int* __restrict__ dst)
{
    int n4 = N_EDGES / 4;
    for (int i = blockIdx.x * 256 + threadIdx.x; i < n4; i += gridDim.x * 256) {
        int4 d = ((const int4*)dst)[i];
        int e = i * 4;
        #pragma unroll
        for (int q = 0; q < 4; q++) {
            int dd = (q == 0) ? d.x : (q == 1) ? d.y : (q == 2) ? d.z : d.w;
            int ee = e + q;
            if (d_flag2[dd]) {
                int j = atomicAdd(&d_cnt[1], 1);
                d_list2[j] = ee;
                d_pos2[ee] = j;
                d_flag1[src[ee]] = 1;
            }
        }
    }
}

__global__ __launch_bounds__(256) void nodes1_kernel()
{
    int v = blockIdx.x * 256 + threadIdx.x;
    if (v < N_NODES && d_flag1[v]) {
        int i = atomicAdd(&d_cnt[3], 1);
        d_nlist1[i] = v;
    }
}

// zero agg_x / agg_attr rows for nlist1 nodes (96 float4 per node)
__global__ __launch_bounds__(256) void zero_agg1_kernel()
{
    int n = d_cnt[3];
    int total = n * 96;
    float4 z = {0.f, 0.f, 0.f, 0.f};
    for (int i = blockIdx.x * 256 + threadIdx.x; i < total; i += gridDim.x * 256) {
        int r = i / 96, q = i % 96;
        int v = d_nlist1[r];
        if (q < 64) ((float4*)(g_aggx + (size_t)v * 256))[q] = z;
        else        ((float4*)(g_agga + (size_t)v * 128))[q - 64] = z;
    }
}

// W' = w_proj @ wme1 (128x128); bvec = b_proj @ wme1 (128)
__global__ __launch_bounds__(128) void combine_w_kernel(
    const float* __restrict__ w_proj, const float* __restrict__ b_proj,
    const float* __restrict__ wme1)
{
    int n = threadIdx.x;
    int k = blockIdx.x;
    float s = 0.f;
    if (k < 128) {
        for (int j = 0; j < 64; j++)
            s += w_proj[k * 64 + j] * wme1[j * 128 + n];
        g_wpm[k * 128 + n] = s;
    } else {
        for (int j = 0; j < 64; j++)
            s += b_proj[j] * wme1[j * 128 + n];
        g_bpm[n] = s;
    }
}

// layer-1 aggregation (ballot over all edges): for flag1[dst], red-add
// x[src] (256f), edge_attr (128f), deg
__global__ __launch_bounds__(256) void agg1_kernel(
    const float* __restrict__ x, const float* __restrict__ eattr,
    const int* __restrict__ src, const int* __restrict__ dst)
{
    int warp = threadIdx.x >> 5, lane = threadIdx.x & 31;
    int e0 = (blockIdx.x * 8 + warp) * 32;
    if (e0 >= N_EDGES) return;
    int e = e0 + lane;
    int d = dst[e];
    bool hit = d_flag1[d] != 0;
    unsigned mask = __ballot_sync(0xffffffffu, hit);
    while (mask) {
        int b = __ffs(mask) - 1;
        mask &= mask - 1;
        int eh = e0 + b;
        int sh = src[eh];
        int dh = __shfl_sync(0xffffffffu, d, b);
        const float4* xr = (const float4*)(x + (size_t)sh * 256);
        redv4(g_aggx + (size_t)dh * 256 + lane * 4, xr[lane]);
        redv4(g_aggx + (size_t)dh * 256 + 128 + lane * 4, xr[lane + 32]);
        const float4* ar = (const float4*)(eattr + (size_t)eh * 128);
        redv4(g_agga + (size_t)dh * 128 + lane * 4, ar[lane]);
        if (lane == 0) atomicAdd(&d_deg[dh], 1);
    }
}

// x1[v] = bs1 + deg[v] * bvec for nlist1 nodes
__global__ __launch_bounds__(256) void seed_x1_kernel(
    float* __restrict__ x1, const float* __restrict__ bs1)
{
    int n = d_cnt[3];
    int total = n * 32;
    for (int i = blockIdx.x * 256 + threadIdx.x; i < total; i += gridDim.x * 256) {
        int r = i >> 5, c = i & 31;
        int v = d_nlist1[r];
        float dg = (float)d_deg[v];
        float4 b = ((const float4*)bs1)[c];
        float4 pv = ((const float4*)g_bpm)[c];
        float4 o = {b.x + dg * pv.x, b.y + dg * pv.y,
                    b.z + dg * pv.z, b.w + dg * pv.w};
        ((float4*)(x1 + (size_t)v * 128))[c] = o;
    }
}

// relu x1 rows in nlist1
__global__ __launch_bounds__(256) void relu_rows_kernel(float* __restrict__ x1)
{
    int n = d_cnt[3];
    int total = n * 32;
    for (int i = blockIdx.x * 256 + threadIdx.x; i < total; i += gridDim.x * 256) {
        int r = i >> 5, c = i & 31;
        float4* p = (float4*)(x1 + (size_t)d_nlist1[r] * 128) + c;
        float4 v = *p;
        v.x = fmaxf(v.x, 0.f); v.y = fmaxf(v.y, 0.f);
        v.z = fmaxf(v.z, 0.f); v.w = fmaxf(v.w, 0.f);
        *p = v;
    }
}

// seed compact 64-wide rows [0,cnt) with bias
__global__ __launch_bounds__(256) void seed_rows64_kernel(
    float* __restrict__ buf, const float* __restrict__ bias, const int* __restrict__ cntp)
{
    int total = *cntp * 16;
    for (int i = blockIdx.x * 256 + threadIdx.x; i < total; i += gridDim.x * 256)
        ((float4*)buf)[i] = ((const float4*)bias)[i & 15];
}

// relu compact 64-wide rows [0,cnt)
__global__ __launch_bounds__(256) void relu_rows64_kernel(
    float* __restrict__ buf, const int* __restrict__ cntp)
{
    int total = *cntp * 16;
    for (int i = blockIdx.x * 256 + threadIdx.x; i < total; i += gridDim.x * 256) {
        float4 v = ((float4*)buf)[i];
        v.x = fmaxf(v.x, 0.f); v.y = fmaxf(v.y, 0.f);
        v.z = fmaxf(v.z, 0.f); v.w = fmaxf(v.w, 0.f);
        ((float4*)buf)[i] = v;
    }
}

// zero aggx2/agge1 and seed x2 = bs2 for nlist2 nodes
__global__ __launch_bounds__(256) void seed2_kernel(
    float* __restrict__ x2, const float* __restrict__ bs2)
{
    int n = d_cnt[0];
    int total = n * 80;
    float4 z = {0.f, 0.f, 0.f, 0.f};
    for (int i = blockIdx.x * 256 + threadIdx.x; i < total; i += gridDim.x * 256) {
        int r = i / 80, q = i % 80;
        int v = d_nlist2[r];
        if (q < 32)      ((float4*)(g_aggx2 + (size_t)v * 128))[q] = z;
        else if (q < 48) ((float4*)(g_agge1 + (size_t)v * 64))[q - 32] = z;
        else ((float4*)(x2 + (size_t)v * 128))[q - 48] = ((const float4*)bs2)[q - 48];
    }
}

// layer-2 aggregation over list2 positions: red-add relu_x1[src], e1 (compact)
__global__ __launch_bounds__(256) void agg2_kernel(
    const float* __restrict__ x1,
    const int* __restrict__ src, const int* __restrict__ dst)
{
    int cnt = d_cnt[1];
    int lane = threadIdx.x & 31;
    for (int i = blockIdx.x * 8 + (threadIdx.x >> 5); i < cnt; i += gridDim.x * 8) {
        int e  = d_list2[i];
        int sh = src[e];
        int dh = dst[e];
        float4 v = ((const float4*)(x1 + (size_t)sh * 128))[lane];
        redv4(g_aggx2 + (size_t)dh * 128 + lane * 4, v);
        if (lane < 16) {
            float4 u = ((const float4*)(g_e1c + (size_t)i * 64))[lane];
            redv4(g_agge1 + (size_t)dh * 64 + lane * 4, u);
        }
    }
}

// ---------------- pipelined gather-GEMM (f32x2 FMA, 8x8 thread tile) ----------------
// OUT=1: store (+bias,+relu) at scat row; OUT=2: red.global.add at scat row.
// gridDim.y = split-K factor (tile-range partition; only valid with OUT=2 or y==1).
template<int BM, int BN, int BK, int NSEG, int OUT>
__global__ __launch_bounds__(256, 2) void gemm_kernel(
    Seg s0, Seg s1, Seg s2,
    const float* __restrict__ bias, int relu_out,
    float* __restrict__ out,
    const int* __restrict__ rowlist,
    const int* __restrict__ scat_map,
    const int* __restrict__ Mptr)
{
    constexpr int ASTR  = BM + 4;
    constexpr int WCOL  = BN / 64;
    constexpr int WPASS = (BK * BN) / 1024;

    const int M    = *Mptr;
    const int row0 = blockIdx.x * BM;
    if (row0 >= M) return;

    extern __shared__ float smem[];
    float* As   = smem;
    float* Wsm  = smem + 2 * BK * ASTR;
    int*   ridx = (int*)(Wsm + 2 * BK * BN);
    int*   sidx = ridx + NSEG * BM;

    Seg segs[3] = {s0, s1, s2};

    const int tid  = threadIdx.x;
    const int warp = tid >> 5;
    const int lane = tid & 31;

    const int wc = warp % WCOL;
    const int wr = warp / WCOL;
    const int ty = wr * 4 + (lane >> 3);
    const int tx = wc * 8 + (lane & 7);

    for (int i = tid; i < BM; i += 256) {
        int r = row0 + i;
        int rc = (r < M) ? r : row0;
        int rid = rowlist[rc];
        #pragma unroll
        for (int s = 0; s < NSEG; s++) {
            const int* g = segs[s].gather;
            ridx[s * BM + i] = (g == POS_GATHER) ? rc : (g ? g[rid] : rid);
        }
        sidx[i] = (scat_map == POS_GATHER) ? rc : (scat_map ? scat_map[rid] : rid);
    }
    __syncthreads();

    const int T0 = segs[0].K / BK;
    const int T1 = T0 + ((NSEG > 1) ? segs[1].K / BK : 0);
    const int T  = T1 + ((NSEG > 2) ? segs[2].K / BK : 0);
    const int ts = T * blockIdx.y / gridDim.y;
    const int te = T * (blockIdx.y + 1) / gridDim.y;

    const int ar_row  = (BM == 256) ? tid : (tid & (BM - 1));
    const int ar_half = (BM == 256) ? 0 : (tid >> 7);

    const float* abase[3];
    #pragma unroll
    for (int s = 0; s < NSEG; s++)
        abase[s] = segs[s].base + (size_t)ridx[s * BM + ar_row] * segs[s].K
                   + ar_half * 16;

    float4 af[4];

    auto map_tile = [&](int t, int& s, int& k0) {
        if (NSEG > 2 && t >= T1)      { s = 2; k0 = (t - T1) * BK; }
        else if (NSEG > 1 && t >= T0) { s = 1; k0 = (t - T0) * BK; }
        else                          { s = 0; k0 = t * BK; }
    };
    auto issueA = [&](int t) {
        int s, k0; map_tile(t, s, k0);
        const float* p = abase[s] + k0;
        #pragma unroll
        for (int q = 0; q < 4; q++) af[q] = *(const float4*)(p + q * 4);
    };
    auto storeA = [&](int buf) {
        float* dst = As + buf * (BK * ASTR);
        #pragma unroll
        for (int q = 0; q < 4; q++) {
            int kk = ar_half * 16 + q * 4;
            dst[(kk + 0) * ASTR + ar_row] = af[q].x;
            dst[(kk + 1) * ASTR + ar_row] = af[q].y;
            dst[(kk + 2) * ASTR + ar_row] = af[q].z;
            dst[(kk + 3) * ASTR + ar_row] = af[q].w;
        }
    };
    auto issueW = [&](int t, int buf) {
        int s, k0; map_tile(t, s, k0);
        const float* wp = segs[s].W + (size_t)k0 * BN;
        uint32_t sa = (uint32_t)__cvta_generic_to_shared(Wsm + buf * (BK * BN));
        #pragma unroll
        for (int ps = 0; ps < WPASS; ps++) {
            int i = tid * 4 + ps * 1024;
            cp16(sa + i * 4, wp + i);
        }
    };

    unsigned long long acc2[4][8];
    #pragma unroll
    for (int p = 0; p < 4; p++)
        #pragma unroll
        for (int j = 0; j < 8; j++) acc2[p][j] = 0ull;

    issueA(ts); storeA(0); issueW(ts, 0); cp_commit();
    if (ts + 1 < te) issueA(ts + 1);
    cp_wait0();
    __syncthreads();

    for (int t = ts; t < te; t++) {
        int buf = (t - ts) & 1;
        if (t + 1 < te) { issueW(t + 1, buf ^ 1); cp_commit(); storeA(buf ^ 1); }
        if (t + 2 < te) issueA(t + 2);

        const float* as = As  + buf * (BK * ASTR);
        const float* ws = Wsm + buf * (BK * BN);
        #pragma unroll
        for (int k = 0; k < BK; k++) {
            ulonglong2 alo = *(const ulonglong2*)(as + k * ASTR + ty * 4);
            ulonglong2 ahi = *(const ulonglong2*)(as + k * ASTR + BM / 2 + ty * 4);
            float4 wlo = *(const float4*)(ws + k * BN + tx * 4);
            float4 whi = *(const float4*)(ws + k * BN + BN / 2 + tx * 4);
            unsigned long long ar[4] = {alo.x, alo.y, ahi.x, ahi.y};
            unsigned long long bd[8] = {
                pack2(wlo.x), pack2(wlo.y), pack2(wlo.z), pack2(wlo.w),
                pack2(whi.x), pack2(whi.y), pack2(whi.z), pack2(whi.w)};
            #pragma unroll
            for (int p = 0; p < 4; p++)
                #pragma unroll
                for (int j = 0; j < 8; j++)
                    ffma2(acc2[p][j], ar[p], bd[j]);
        }
        cp_wait0();
        __syncthreads();
    }

    float bv[8];
    if (OUT == 1) {
        #pragma unroll
        for (int j = 0; j < 4; j++) {
            bv[j]     = bias ? bias[tx * 4 + j] : 0.f;
            bv[4 + j] = bias ? bias[BN / 2 + tx * 4 + j] : 0.f;
        }
    }
    #pragma unroll
    for (int h = 0; h < 8; h++) {
        int hh = h & 3;
        int p  = ((h >> 2) << 1) | (hh >> 1);
        int c  = hh & 1;
        int rl = (h < 4) ? (ty * 4 + hh) : (BM / 2 + ty * 4 + hh);
        if (row0 + rl < M) {
            float* op = out + (size_t)sidx[rl] * BN;
            if (OUT == 2) {
                float v0 = sel2(acc2[p][0], c), v1 = sel2(acc2[p][1], c);
                float v2 = sel2(acc2[p][2], c), v3 = sel2(acc2[p][3], c);
                asm volatile("red.global.add.v4.f32 [%0], {%1,%2,%3,%4};"
                             :: "l"(op + tx * 4), "f"(v0), "f"(v1), "f"(v2), "f"(v3)
                             : "memory");
                float u0 = sel2(acc2[p][4], c), u1 = sel2(acc2[p][5], c);
                float u2 = sel2(acc2[p][6], c), u3 = sel2(acc2[p][7], c);
                asm volatile("red.global.add.v4.f32 [%0], {%1,%2,%3,%4};"
                             :: "l"(op + BN / 2 + tx * 4), "f"(u0), "f"(u1), "f"(u2), "f"(u3)
                             : "memory");
            } else {
                float4 o0, o1;
                o0.x = sel2(acc2[p][0], c) + bv[0];
                o0.y = sel2(acc2[p][1], c) + bv[1];
                o0.z = sel2(acc2[p][2], c) + bv[2];
                o0.w = sel2(acc2[p][3], c) + bv[3];
                o1.x = sel2(acc2[p][4], c) + bv[4];
                o1.y = sel2(acc2[p][5], c) + bv[5];
                o1.z = sel2(acc2[p][6], c) + bv[6];
                o1.w = sel2(acc2[p][7], c) + bv[7];
                if (relu_out) {
                    o0.x = fmaxf(o0.x, 0.f); o0.y = fmaxf(o0.y, 0.f);
                    o0.z = fmaxf(o0.z, 0.f); o0.w = fmaxf(o0.w, 0.f);
                    o1.x = fmaxf(o1.x, 0.f); o1.y = fmaxf(o1.y, 0.f);
                    o1.z = fmaxf(o1.z, 0.f); o1.w = fmaxf(o1.w, 0.f);
                }
                *(float4*)(op + tx * 4) = o0;
                *(float4*)(op + BN / 2 + tx * 4) = o1;
            }
        }
    }
}

// ---------------- layer-3 master kernels ----------------

__global__ __launch_bounds__(256) void master_node_kernel(
    const float* __restrict__ x2, const float* __restrict__ ws3,
    const float* __restrict__ bs3, float* __restrict__ out)
{
    int g = blockIdx.x;
    int c = threadIdx.x;
    const float* xr = x2 + (size_t)g * NODES_PER_GRAPH * 128;
    float acc = bs3[c];
    #pragma unroll 8
    for (int k = 0; k < 128; k++)
        acc += fmaxf(xr[k], 0.f) * ws3[(size_t)k * 256 + c];
    out[(size_t)g * 256 + c] = acc;
}

// out[g] += relu_x2[src]@wmx3 + e2@wme3 over list3 positions (warp per edge)
__global__ __launch_bounds__(256) void master_edge3_kernel(
    const float* __restrict__ x2,
    const int* __restrict__ src, const int* __restrict__ dst,
    const float* __restrict__ wmx3, const float* __restrict__ wme3,
    float* __restrict__ out)
{
    int cnt = d_cnt[2];
    int lane = threadIdx.x & 31;
    for (int i = blockIdx.x * 8 + (threadIdx.x >> 5); i < cnt; i += gridDim.x * 8) {
        int e  = d_list3[i];
        int sh = src[e];
        int g  = dst[e] / NODES_PER_GRAPH;
        float acc[8];
        #pragma unroll
        for (int j = 0; j < 8; j++) acc[j] = 0.f;
        const float* xr = x2 + (size_t)sh * 128;
        for (int k = 0; k < 128; k++) {
            float a = fmaxf(xr[k], 0.f);
            const float* wr = wmx3 + (size_t)k * 256;
            #pragma unroll
            for (int j = 0; j < 8; j++) acc[j] += a * wr[lane + j * 32];
        }
        const float* er = g_e2c + (size_t)i * 64;
        for (int k = 0; k < 64; k++) {
            float a = er[k];
            const float* wr = wme3 + (size_t)k * 256;
            #pragma unroll
            for (int j = 0; j < 8; j++) acc[j] += a * wr[lane + j * 32];
        }
        float* op = out + (size_t)g * 256;
        #pragma unroll
        for (int j = 0; j < 8; j++) atomicAdd(op + lane + j * 32, acc[j]);
    }
}

template<int BM, int BN, int BK, int NSEG>
static int smem_bytes() {
    constexpr int ASTR = BM + 4;
    return (2 * BK * ASTR + 2 * BK * BN) * 4 + NSEG * BM * 4 + BM * 4;
}

extern "C" void kernel_launch(void* const* d_in, const int* in_sizes, int n_in,
                              void* d_out, int out_size)
{
    const float* x         = (const float*)d_in[0];
    const int*   edge_idx  = (const int*)d_in[1];
    const float* edge_attr = (const float*)d_in[2];
    const float* w_proj    = (const float*)d_in[4];
    const float* b_proj    = (const float*)d_in[5];
    const float* P[30];
    for (int i = 0; i < 30 && i < n_in; i++) P[i] = (const float*)d_in[i];

    const int* src = edge_idx;
    const int* dst = edge_idx + N_EDGES;
    float* out = (float*)d_out;

    void* p;
    cudaGetSymbolAddress(&p, g_x1);     float* x1_p    = (float*)p;
    cudaGetSymbolAddress(&p, g_x2);     float* x2_p    = (float*)p;
    cudaGetSymbolAddress(&p, g_aggx);   float* aggx_p  = (float*)p;
    cudaGetSymbolAddress(&p, g_agga);   float* agga_p  = (float*)p;
    cudaGetSymbolAddress(&p, g_aggx2);  float* aggx2_p = (float*)p;
    cudaGetSymbolAddress(&p, g_agge1);  float* agge1_p = (float*)p;
    cudaGetSymbolAddress(&p, g_ec);     float* ec_p    = (float*)p;
    cudaGetSymbolAddress(&p, g_e1c);    float* e1c_p   = (float*)p;
    cudaGetSymbolAddress(&p, g_e2c);    float* e2c_p   = (float*)p;
    cudaGetSymbolAddress(&p, g_wpm);    float* wpm_p   = (float*)p;
    cudaGetSymbolAddress(&p, d_list2);  const int* l2  = (const int*)p;
    cudaGetSymbolAddress(&p, d_list3);  const int* l3  = (const int*)p;
    cudaGetSymbolAddress(&p, d_pos2);   const int* pos2 = (const int*)p;
    cudaGetSymbolAddress(&p, d_nlist1); const int* n1  = (const int*)p;
    cudaGetSymbolAddress(&p, d_nlist2); const int* n2  = (const int*)p;
    cudaGetSymbolAddress(&p, d_cnt);    const int* cnt = (const int*)p;
    const int* c_n2 = cnt + 0;
    const int* c_l2 = cnt + 1;
    const int* c_l3 = cnt + 2;
    const int* c_n1 = cnt + 3;

    // one-time: smem attrs + side streams/events (created on the uncaptured
    // correctness call; reused under capture)
    static cudaStream_t sB = nullptr, sC = nullptr;
    static cudaEvent_t evRoot, evCW, evMark, evL2, evS2, evE1, evX1, evE2;
    if (!sB) {
        cudaFuncSetAttribute(gemm_kernel<256, 64, 16, 1, 1>,
            cudaFuncAttributeMaxDynamicSharedMemorySize, smem_bytes<256, 64, 16, 1>());
        cudaFuncSetAttribute(gemm_kernel<256, 64, 16, 3, 2>,
            cudaFuncAttributeMaxDynamicSharedMemorySize, smem_bytes<256, 64, 16, 3>());
        cudaFuncSetAttribute(gemm_kernel<128, 128, 32, 3, 2>,
            cudaFuncAttributeMaxDynamicSharedMemorySize, smem_bytes<128, 128, 32, 3>());
        cudaStreamCreateWithFlags(&sB, cudaStreamNonBlocking);
        cudaStreamCreateWithFlags(&sC, cudaStreamNonBlocking);
        cudaEventCreateWithFlags(&evRoot, cudaEventDisableTiming);
        cudaEventCreateWithFlags(&evCW,   cudaEventDisableTiming);
        cudaEventCreateWithFlags(&evMark, cudaEventDisableTiming);
        cudaEventCreateWithFlags(&evL2,   cudaEventDisableTiming);
        cudaEventCreateWithFlags(&evS2,   cudaEventDisableTiming);
        cudaEventCreateWithFlags(&evE1,   cudaEventDisableTiming);
        cudaEventCreateWithFlags(&evX1,   cudaEventDisableTiming);
        cudaEventCreateWithFlags(&evE2,   cudaEventDisableTiming);
    }

    Seg z = {nullptr, nullptr, nullptr, 0};
    const int NGRID = (N_NODES + 255) / 256;

    // ---- fork root: stream C does combine_w concurrently with marking ----
    cudaEventRecord(evRoot, 0);
    cudaStreamWaitEvent(sC, evRoot, 0);
    combine_w_kernel<<<129, 128, 0, sC>>>(w_proj, b_proj, P[9]);   // P[9]=wme1
    cudaEventRecord(evCW, sC);

    // ---- main chain A: marking ----
    zero_kernel<<<256, 256>>>();
    mark2_scan<<<1024, 256>>>(src, dst);          // flag2,nlist2,flag1,list3
    cudaEventRecord(evMark, 0);
    cudaStreamWaitEvent(sC, evMark, 0);
    seed2_kernel<<<256, 256, 0, sC>>>(x2_p, P[15]);   // needs nlist2
    cudaEventRecord(evS2, sC);

    list2_scan<<<1024, 256>>>(src, dst);          // list2,pos2,flag1|=src
    cudaEventRecord(evL2, 0);

    // ---- chain B (stream sB): e0 -> e1 (hidden under agg1/x1) ----
    cudaStreamWaitEvent(sB, evL2, 0);
    {
        Seg a = {edge_attr, nullptr, w_proj, 128};
        gemm_kernel<256, 64, 16, 1, 1>
            <<<CAP_L2 / 256, 256, smem_bytes<256, 64, 16, 1>(), sB>>>(
            a, z, z, b_proj, 0, ec_p, l2, POS_GATHER, c_l2);
    }
    seed_rows64_kernel<<<256, 256, 0, sB>>>(e1c_p, P[13], c_l2);
    {
        Seg a = {x,    src,        P[10], 256};
        Seg b = {x,    dst,        P[11], 256};
        Seg c = {ec_p, POS_GATHER, P[12], 64};
        gemm_kernel<256, 64, 16, 3, 2>
            <<<dim3(CAP_L2 / 256, 2), 256, smem_bytes<256, 64, 16, 3>(), sB>>>(
            a, b, c, nullptr, 0, e1c_p, l2, POS_GATHER, c_l2);
    }
    relu_rows64_kernel<<<256, 256, 0, sB>>>(e1c_p, c_l2);
    cudaEventRecord(evE1, sB);
    seed_rows64_kernel<<<64, 256, 0, sB>>>(e2c_p, P[21], c_l3);

    // ---- chain A: node aggregation + x1 ----
    nodes1_kernel<<<NGRID, 256>>>();              // flag1 complete (both writers on A)
    zero_agg1_kernel<<<1024, 256>>>();
    agg1_kernel<<<N_EDGES / 256, 256>>>(x, edge_attr, src, dst);
    cudaStreamWaitEvent(0, evCW, 0);              // bpm/wpm ready
    seed_x1_kernel<<<512, 256>>>(x1_p, P[7]);
    {
        Seg a = {x,      nullptr, P[6],  256};
        Seg b = {aggx_p, nullptr, P[8],  256};
        Seg c = {agga_p, nullptr, wpm_p, 128};
        gemm_kernel<128, 128, 32, 3, 2>
            <<<dim3(CAP_N1 / 128, 2), 256, smem_bytes<128, 128, 32, 3>()>>>(
            a, b, c, nullptr, 0, x1_p, n1, nullptr, c_n1);
    }
    relu_rows_kernel<<<512, 256>>>(x1_p);
    cudaEventRecord(evX1, 0);

    // ---- chain B: e2 (needs relu_x1 + e1c) ----
    cudaStreamWaitEvent(sB, evX1, 0);
    {
        Seg a = {x1_p,  src,   P[18], 128};
        Seg b = {x1_p,  dst,   P[19], 128};
        Seg c = {e1c_p, pos2,  P[20], 64};
        gemm_kernel<256, 64, 16, 3, 2>
            <<<dim3(CAP_L3 / 256, 4), 256, smem_bytes<256, 64, 16, 3>(), sB>>>(
            a, b, c, nullptr, 0, e2c_p, l3, POS_GATHER, c_l3);
    }
    relu_rows64_kernel<<<64, 256, 0, sB>>>(e2c_p, c_l3);
    cudaEventRecord(evE2, sB);

    // ---- chain A: layer 2 + masters ----
    cudaStreamWaitEvent(0, evE1, 0);
    cudaStreamWaitEvent(0, evS2, 0);
    agg2_kernel<<<512, 256>>>(x1_p, src, dst);
    {
        Seg a = {x1_p,    nullptr, P[14], 128};
        Seg b = {aggx2_p, nullptr, P[16], 128};
        Seg c = {agge1_p, nullptr, P[17], 64};
        gemm_kernel<128, 128, 32, 3, 2>
            <<<dim3(CAP_N2 / 128, 4), 256, smem_bytes<128, 128, 32, 3>()>>>(
            a, b, c, nullptr, 0, x2_p, n2, nullptr, c_n2);
    }
    master_node_kernel<<<N_GRAPHS, 256>>>(x2_p, P[22], P[23], out);
    cudaStreamWaitEvent(0, evE2, 0);
    master_edge3_kernel<<<128, 256>>>(x2_p, src, dst, P[24], P[25], out);
}